// round 11
// baseline (speedup 1.0000x reference)
#include <cuda_runtime.h>
#include <cuda_bf16.h>
#include <cstdint>
#include <math.h>

#define HDIM 96
#define WDIM 96
#define PIX  (HDIM*WDIM)     // 9216
#define NB   4
#define CINF 1024
#define CINT 512
#define DD   4
#define QD   9
#define QQ   81
#define NPIX (NB*PIX)        // 36864

// ------------------------- scratch (device globals) -------------------------
__device__ __nv_bfloat16 g_xT  [(size_t)NPIX * CINF];      // bf16 [p][1024]
__device__ __nv_bfloat16 g_xrT [(size_t)NPIX * CINF];      // bf16 [p][1024]
__device__ __nv_bfloat16 g_thb [(size_t)NPIX * CINT];      // bf16 theta NHWC [p][512]
__device__ __nv_bfloat16 g_gphib[(size_t)NPIX * 2 * CINT]; // bf16 g|phi NHWC [p][1024]
__device__ __nv_bfloat16 g_ybf [(size_t)NPIX * CINT];      // bf16 y NHWC [p][512]
__device__ __nv_bfloat16 g_wth [(size_t)CINT * CINF];
__device__ __nv_bfloat16 g_wgp [(size_t)CINF * CINF];      // (wg;wphi)
__device__ __nv_bfloat16 g_wo  [(size_t)CINF * CINT];

// ------------------------- helpers ------------------------------------------
__device__ __forceinline__ uint32_t smem_u32(const void* p) {
    uint32_t a;
    asm("{ .reg .u64 t; cvta.to.shared.u64 t, %1; cvt.u32.u64 %0, t; }" : "=r"(a) : "l"(p));
    return a;
}
#define CP_ASYNC16(dst, src) \
    asm volatile("cp.async.cg.shared.global [%0], [%1], 16;" :: "r"(dst), "l"(src))
#define CP_ASYNC16Z(dst, src, sz) \
    asm volatile("cp.async.cg.shared.global [%0], [%1], 16, %2;" :: "r"(dst), "l"(src), "r"(sz))
#define CP_COMMIT() asm volatile("cp.async.commit_group;" ::: "memory")
#define CP_WAIT(n)  asm volatile("cp.async.wait_group %0;" :: "n"(n) : "memory")

#define LDSM4(r, a) \
    asm volatile("ldmatrix.sync.aligned.m8n8.x4.shared.b16 {%0,%1,%2,%3}, [%4];" \
        : "=r"((r)[0]), "=r"((r)[1]), "=r"((r)[2]), "=r"((r)[3]) : "r"(a))
#define LDSM4T(r, a) \
    asm volatile("ldmatrix.sync.aligned.m8n8.x4.trans.shared.b16 {%0,%1,%2,%3}, [%4];" \
        : "=r"((r)[0]), "=r"((r)[1]), "=r"((r)[2]), "=r"((r)[3]) : "r"(a))

#define MMA16816(d, a, bb0, bb1) \
    asm volatile("mma.sync.aligned.m16n8k16.row.col.f32.bf16.bf16.f32 " \
        "{%0,%1,%2,%3},{%4,%5,%6,%7},{%8,%9},{%0,%1,%2,%3};" \
        : "+f"((d)[0]), "+f"((d)[1]), "+f"((d)[2]), "+f"((d)[3]) \
        : "r"((a)[0]), "r"((a)[1]), "r"((a)[2]), "r"((a)[3]), "r"(bb0), "r"(bb1))

// 64-bf16-wide tile swizzle (128B rows, 8 x 16B chunks)
__device__ __forceinline__ uint32_t sw128(int row, int ch) {
    return (uint32_t)(row * 128 + ((ch ^ (row & 7)) << 4));
}

// ------------------------- transpose + convert (x & x_ref merged) ------------
__global__ void conv_tr2_k(const float* __restrict__ x, const float* __restrict__ xr,
                           __nv_bfloat16* __restrict__ dx, __nv_bfloat16* __restrict__ dxr)
{
    __shared__ float ts[64][33];
    const int tx = threadIdx.x, ty = threadIdx.y;
    const int z = blockIdx.z;
    const int n = z & (NB - 1);
    const float* src = (z < NB) ? x : xr;
    __nv_bfloat16* dst = (z < NB) ? dx : dxr;
    const int p0 = blockIdx.x * 32, c0 = blockIdx.y * 64;
    #pragma unroll
    for (int r = 0; r < 8; r++) {
        int cl = ty + r * 8;
        ts[cl][tx] = src[((size_t)n * CINF + c0 + cl) * PIX + p0 + tx];
    }
    __syncthreads();
    #pragma unroll
    for (int r = 0; r < 4; r++) {
        int pl = ty + r * 8;
        __nv_bfloat162 v = __floats2bfloat162_rn(ts[2 * tx][pl], ts[2 * tx + 1][pl]);
        *(__nv_bfloat162*)(dst + ((size_t)n * PIX + p0 + pl) * CINF + c0 + 2 * tx) = v;
    }
}

// all four weight tensors are 524288 elements each
__global__ void cvt4_k(const float* __restrict__ s0, const float* __restrict__ s1,
                       const float* __restrict__ s2, const float* __restrict__ s3,
                       __nv_bfloat16* __restrict__ d0, __nv_bfloat16* __restrict__ d1,
                       __nv_bfloat16* __restrict__ d2, __nv_bfloat16* __restrict__ d3)
{
    int i = blockIdx.x * 256 + threadIdx.x;
    int seg = i >> 19, off = i & 524287;
    const float* s = (seg == 0) ? s0 : (seg == 1) ? s1 : (seg == 2) ? s2 : s3;
    __nv_bfloat16* d = (seg == 0) ? d0 : (seg == 1) ? d1 : (seg == 2) ? d2 : d3;
    d[off] = __float2bfloat16(s[off]);
}

// ------------------------- merged projection GEMM ----------------------------
// (unchanged from R10 — 591.8us passing version)
__global__ __launch_bounds__(256, 2)
void proj_gemm(const __nv_bfloat16* __restrict__ wth, const __nv_bfloat16* __restrict__ wgp,
               const __nv_bfloat16* __restrict__ xT, const __nv_bfloat16* __restrict__ xrT,
               const float* __restrict__ bth, const float* __restrict__ bg,
               const float* __restrict__ bphi,
               __nv_bfloat16* __restrict__ thb, __nv_bfloat16* __restrict__ gphib)
{
    extern __shared__ char smem[];   // 2 stages x (A 16KB | B 16KB)

    const int t = threadIdx.x, lane = t & 31, wid = t >> 5;
    const int warp_m = wid >> 2, warp_n = wid & 3;
    const int n = blockIdx.z, pbase = blockIdx.x * 128;
    const int by = blockIdx.y;
    const bool th = (by < 4);
    const int obase = (th ? by : by - 4) * 128;
    const __nv_bfloat16* A  = th ? wth : wgp;
    const __nv_bfloat16* Bx = th ? xT : xrT;
    __nv_bfloat16* out = th ? thb : gphib;
    const int ldo = th ? CINT : 2 * CINT;
    const float* b0 = th ? bth : bg;
    const float* b1 = th ? bth : bphi;
    const int K = CINF, NC = K >> 6;   // 16

    const __nv_bfloat16* Ab = A + (size_t)obase * K;
    const __nv_bfloat16* Bb = Bx + ((size_t)n * PIX + pbase) * K;
    const uint32_t sbase = smem_u32(smem);

    float acc[4][4][4];
    #pragma unroll
    for (int mi = 0; mi < 4; mi++)
        #pragma unroll
        for (int ni = 0; ni < 4; ni++)
            #pragma unroll
            for (int r = 0; r < 4; r++) acc[mi][ni][r] = 0.f;

    const int rowL = t >> 3, chL = t & 7;
    auto issue = [&](int c) {
        const int k0 = c << 6;
        const uint32_t st = sbase + (c & 1) * 32768;
        #pragma unroll
        for (int i = 0; i < 4; i++) {
            int row = rowL + i * 32;
            CP_ASYNC16(st + sw128(row, chL), Ab + (size_t)row * K + k0 + chL * 8);
        }
        #pragma unroll
        for (int i = 0; i < 4; i++) {
            int row = rowL + i * 32;
            CP_ASYNC16(st + 16384 + sw128(row, chL), Bb + (size_t)row * K + k0 + chL * 8);
        }
        CP_COMMIT();
    };

    issue(0);
    const int rl = lane & 15, cs = lane >> 4;

    for (int c = 0; c < NC; c++) {
        CP_WAIT(0);
        __syncthreads();
        if (c + 1 < NC) issue(c + 1);

        const uint32_t stA = sbase + (c & 1) * 32768;
        const uint32_t stB = stA + 16384;
        #pragma unroll
        for (int kh = 0; kh < 4; kh++) {
            const int ch = 2 * kh + cs;
            uint32_t af[4][4], bf[2][4];
            #pragma unroll
            for (int mi = 0; mi < 4; mi++)
                LDSM4(af[mi], stA + sw128(warp_m * 64 + mi * 16 + rl, ch));
            #pragma unroll
            for (int g = 0; g < 2; g++)
                LDSM4(bf[g], stB + sw128(warp_n * 32 + g * 16 + rl, ch));
            #pragma unroll
            for (int mi = 0; mi < 4; mi++)
                #pragma unroll
                for (int g = 0; g < 2; g++) {
                    MMA16816(acc[mi][2 * g + 0], af[mi], bf[g][0], bf[g][2]);
                    MMA16816(acc[mi][2 * g + 1], af[mi], bf[g][1], bf[g][3]);
                }
        }
    }

    // epilogue: transpose via SMEM -> coalesced bf16 NHWC rows
    __syncthreads();
    __nv_bfloat16* S = (__nv_bfloat16*)smem;   // [128 p][136 o]
    #pragma unroll
    for (int mi = 0; mi < 4; mi++) {
        #pragma unroll
        for (int h = 0; h < 2; h++) {
            const int ol = warp_m * 64 + mi * 16 + (lane >> 2) + h * 8;
            const int og = obase + ol;
            const float bias = (og < CINT) ? b0[og] : b1[og - CINT];
            #pragma unroll
            for (int ni = 0; ni < 4; ni++) {
                const int pl = warp_n * 32 + ni * 8 + (lane & 3) * 2;
                S[(size_t)pl * 136 + ol]       = __float2bfloat16(acc[mi][ni][2 * h + 0] + bias);
                S[(size_t)(pl + 1) * 136 + ol] = __float2bfloat16(acc[mi][ni][2 * h + 1] + bias);
            }
        }
    }
    __syncthreads();
    #pragma unroll
    for (int s = 0; s < 16; s++) {
        const int pl = s * 8 + wid;
        uint2 v = *(uint2*)&S[(size_t)pl * 136 + lane * 4];
        *(uint2*)(out + ((size_t)n * PIX + pbase + pl) * ldo + obase + lane * 4) = v;
    }
}

// ------------------------- final GEMM (residual, fp32 NCHW) ------------------
// (unchanged from R10)
__global__ __launch_bounds__(256, 2)
void final_gemm(const __nv_bfloat16* __restrict__ A, const __nv_bfloat16* __restrict__ B,
                const float* __restrict__ b0, float* __restrict__ out,
                const float* __restrict__ resid)
{
    extern __shared__ char smem[];   // 2 stages x 32KB

    const int t = threadIdx.x, lane = t & 31, wid = t >> 5;
    const int warp_m = wid >> 2, warp_n = wid & 3;
    const int n = blockIdx.z, pbase = blockIdx.x * 128, obase = blockIdx.y * 128;
    const int K = CINT, NC = K >> 6;   // 8

    const __nv_bfloat16* Ab = A + (size_t)obase * K;
    const __nv_bfloat16* Bb = B + ((size_t)n * PIX + pbase) * K;
    const uint32_t sbase = smem_u32(smem);

    float acc[4][4][4];
    #pragma unroll
    for (int mi = 0; mi < 4; mi++)
        #pragma unroll
        for (int ni = 0; ni < 4; ni++)
            #pragma unroll
            for (int r = 0; r < 4; r++) acc[mi][ni][r] = 0.f;

    const int rowL = t >> 3, chL = t & 7;
    auto issue = [&](int c) {
        const int k0 = c << 6;
        const uint32_t st = sbase + (c & 1) * 32768;
        #pragma unroll
        for (int i = 0; i < 4; i++) {
            int row = rowL + i * 32;
            CP_ASYNC16(st + sw128(row, chL), Ab + (size_t)row * K + k0 + chL * 8);
        }
        #pragma unroll
        for (int i = 0; i < 4; i++) {
            int row = rowL + i * 32;
            CP_ASYNC16(st + 16384 + sw128(row, chL), Bb + (size_t)row * K + k0 + chL * 8);
        }
        CP_COMMIT();
    };

    issue(0);
    const int rl = lane & 15, cs = lane >> 4;

    for (int c = 0; c < NC; c++) {
        CP_WAIT(0);
        __syncthreads();
        if (c + 1 < NC) issue(c + 1);

        const uint32_t stA = sbase + (c & 1) * 32768;
        const uint32_t stB = stA + 16384;
        #pragma unroll
        for (int kh = 0; kh < 4; kh++) {
            const int ch = 2 * kh + cs;
            uint32_t af[4][4], bf[2][4];
            #pragma unroll
            for (int mi = 0; mi < 4; mi++)
                LDSM4(af[mi], stA + sw128(warp_m * 64 + mi * 16 + rl, ch));
            #pragma unroll
            for (int g = 0; g < 2; g++)
                LDSM4(bf[g], stB + sw128(warp_n * 32 + g * 16 + rl, ch));
            #pragma unroll
            for (int mi = 0; mi < 4; mi++)
                #pragma unroll
                for (int g = 0; g < 2; g++) {
                    MMA16816(acc[mi][2 * g + 0], af[mi], bf[g][0], bf[g][2]);
                    MMA16816(acc[mi][2 * g + 1], af[mi], bf[g][1], bf[g][3]);
                }
        }
    }

    // epilogue: stage to SMEM, then fully-coalesced resid add + store
    float* Es = (float*)smem;   // [64 o][132 p]
    #pragma unroll
    for (int og = 0; og < 2; og++) {
        __syncthreads();
        if (warp_m == og) {
            #pragma unroll
            for (int mi = 0; mi < 4; mi++)
                #pragma unroll
                for (int h = 0; h < 2; h++) {
                    const int row = mi * 16 + (lane >> 2) + h * 8;
                    #pragma unroll
                    for (int ni = 0; ni < 4; ni++) {
                        const int col = warp_n * 32 + ni * 8 + (lane & 3) * 2;
                        Es[(size_t)row * 132 + col]     = acc[mi][ni][2 * h + 0];
                        Es[(size_t)row * 132 + col + 1] = acc[mi][ni][2 * h + 1];
                    }
                }
        }
        __syncthreads();
        #pragma unroll
        for (int s = 0; s < 8; s++) {
            const int row = s * 8 + wid;
            const int o = obase + og * 64 + row;
            const size_t addr = ((size_t)n * CINF + o) * PIX + pbase + lane * 4;
            float4 e = *(float4*)&Es[(size_t)row * 132 + lane * 4];
            float4 r = *(const float4*)(resid + addr);
            const float bias = b0[o];
            float4 v;
            v.x = e.x + bias + r.x; v.y = e.y + bias + r.y;
            v.z = e.z + bias + r.z; v.w = e.w + bias + r.w;
            *(float4*)(out + addr) = v;
        }
    }
}

// ------------------------- fused corr + softmax + assemble -------------------
// Per 8x8 pixel tile (halo 16x16 = 256):
//   phase1: C[64][256] = theta_tile @ phi_halo^T  (c64 chunks, 2-stage)
//   phase2: per-pixel softmax over 81 halo cols -> PW bf16 [64][256] (+pad)
//   phase3: y[64][512] = PW @ g_halo              (64-row chunks, 2-stage)
// SMEM: [0,33792) PW ; [33792,+81920) region X (stages / Cs fp32 [64][266]) ; invs
__global__ __launch_bounds__(256, 2)
void fused_attn_k(const __nv_bfloat16* __restrict__ theta,
                  const __nv_bfloat16* __restrict__ gphi,
                  __nv_bfloat16* __restrict__ y)
{
    extern __shared__ char smem[];
    char*  Xr   = smem + 33792;
    float* Cs   = (float*)Xr;                       // [64][266] fp32 (68096 B)
    float* invs = (float*)(smem + 33792 + 81920);   // [64]

    const int t = threadIdx.x, lane = t & 31, wid = t >> 5;
    const int warp_m = wid >> 2, warp_n = wid & 3;  // 2 x 4
    const int rl = lane & 15, cs = lane >> 4;
    const int n = blockIdx.z, h0 = blockIdx.y * 8, w0 = blockIdx.x * 8;

    const uint32_t sbX  = smem_u32(Xr);
    const uint32_t sbPW = smem_u32(smem);
    const __nv_bfloat16* gbase = gphi + (size_t)n * PIX * 1024;

    float acc[2][8][4];
    #pragma unroll
    for (int a = 0; a < 2; a++)
        #pragma unroll
        for (int b = 0; b < 8; b++)
            #pragma unroll
            for (int c = 0; c < 4; c++) acc[a][b][c] = 0.f;

    // ---------------- phase 1: corr GEMM, 64-channel chunks, 2-stage ----------
    // stage: A (theta 64px x 64ch, sw128) 8KB | B (phi halo 256 x 64ch) 32KB
    const int rowA0 = t >> 3, chA0 = t & 7;   // A: 2 loads/thread
    const __nv_bfloat16* thsrc0 =
        theta + ((size_t)n * PIX + (h0 + (rowA0 >> 3)) * WDIM + (w0 + (rowA0 & 7))) * CINT + chA0 * 8;
    const int rowA1 = (t + 256) >> 3, chA1 = t & 7;
    const __nv_bfloat16* thsrc1 =
        theta + ((size_t)n * PIX + (h0 + (rowA1 >> 3)) * WDIM + (w0 + (rowA1 & 7))) * CINT + chA1 * 8;

    auto issue1 = [&](int c) {
        const int c0 = c << 6;
        const uint32_t st = sbX + (c & 1) * 40960;
        CP_ASYNC16(st + sw128(rowA0, chA0), thsrc0 + c0);
        CP_ASYNC16(st + sw128(rowA1, chA1), thsrc1 + c0);
        #pragma unroll
        for (int i = 0; i < 8; i++) {
            int idx = t + i * 256;
            int row = idx >> 3, ch = idx & 7;
            int hy = h0 + (row >> 4) - DD, hx = w0 + (row & 15) - DD;
            bool ok = (hy >= 0 && hy < HDIM && hx >= 0 && hx < WDIM);
            const __nv_bfloat16* src = gbase +
                (ok ? ((size_t)(hy * WDIM + hx) * 1024 + 512 + c0 + ch * 8) : 0);
            CP_ASYNC16Z(st + 8192 + sw128(row, ch), src, ok ? 16u : 0u);
        }
        CP_COMMIT();
    };

    issue1(0);
    for (int c = 0; c < 8; c++) {
        CP_WAIT(0);
        __syncthreads();
        if (c + 1 < 8) issue1(c + 1);
        const uint32_t stA = sbX + (c & 1) * 40960;
        const uint32_t stB = stA + 8192;
        #pragma unroll
        for (int kh = 0; kh < 4; kh++) {
            const int ch = 2 * kh + cs;
            uint32_t af[2][4], bm[4][4];
            #pragma unroll
            for (int mi = 0; mi < 2; mi++)
                LDSM4(af[mi], stA + sw128(warp_m * 32 + mi * 16 + rl, ch));
            #pragma unroll
            for (int nf = 0; nf < 4; nf++)
                LDSM4(bm[nf], stB + sw128(warp_n * 64 + nf * 16 + rl, ch));
            #pragma unroll
            for (int mi = 0; mi < 2; mi++)
                #pragma unroll
                for (int nf = 0; nf < 4; nf++) {
                    MMA16816(acc[mi][2 * nf + 0], af[mi], bm[nf][0], bm[nf][2]);
                    MMA16816(acc[mi][2 * nf + 1], af[mi], bm[nf][1], bm[nf][3]);
                }
        }
    }
    __syncthreads();   // stages dead; write C to smem (overlays stage region)

    #pragma unroll
    for (int mi = 0; mi < 2; mi++)
        #pragma unroll
        for (int ni = 0; ni < 8; ni++) {
            const int r0  = warp_m * 32 + mi * 16 + (lane >> 2);
            const int col = warp_n * 64 + ni * 8 + 2 * (lane & 3);
            *(float2*)&Cs[(size_t)r0 * 266 + col]       = make_float2(acc[mi][ni][0], acc[mi][ni][1]);
            *(float2*)&Cs[(size_t)(r0 + 8) * 266 + col] = make_float2(acc[mi][ni][2], acc[mi][ni][3]);
        }
    __syncthreads();

    // ---------------- phase 2: softmax -> PW bf16 ----------------
    if (t < 64) {
        const int py = t >> 3, pxx = t & 7;
        uint32_t* pwz = (uint32_t*)(smem + t * 528);
        #pragma unroll 4
        for (int i = 0; i < 132; i++) pwz[i] = 0;
        const float SC = 0.051031036307982884f;   // 256/(512*sqrt(96))
        float m = -1e30f;
        #pragma unroll
        for (int dy = 0; dy < QD; dy++)
            #pragma unroll
            for (int dx = 0; dx < QD; dx++)
                m = fmaxf(m, Cs[(size_t)t * 266 + (py + dy) * 16 + pxx + dx] * SC);
        float s = 0.f;
        __nv_bfloat16* pwrow = (__nv_bfloat16*)(smem + t * 528);
        #pragma unroll
        for (int dy = 0; dy < QD; dy++)
            #pragma unroll
            for (int dx = 0; dx < QD; dx++) {
                const int col = (py + dy) * 16 + pxx + dx;
                float e = __expf(Cs[(size_t)t * 266 + col] * SC - m);
                s += e;
                pwrow[col] = __float2bfloat16(e);
            }
        invs[t] = 1.f / s;
    }
    __syncthreads();

    // ---------------- phase 3: assemble GEMM, 64-row chunks, 2-stage ----------
    // stage: 64 halo rows x 512B (32 x 16B ch), swizzle ch ^ (row & 7). 32KB.
    for (int half = 0; half < 2; half++) {
        const int cbase = half * 256;
        #pragma unroll
        for (int a = 0; a < 2; a++)
            #pragma unroll
            for (int b = 0; b < 8; b++)
                #pragma unroll
                for (int c = 0; c < 4; c++) acc[a][b][c] = 0.f;

        auto issue3 = [&](int kk) {
            const uint32_t st = sbX + (kk & 1) * 32768;
            #pragma unroll
            for (int i = 0; i < 8; i++) {
                int idx = t + i * 256;
                int row = idx >> 5, ch = idx & 31;
                int hp = kk * 64 + row;
                int hy = h0 + (hp >> 4) - DD, hx = w0 + (hp & 15) - DD;
                bool ok = (hy >= 0 && hy < HDIM && hx >= 0 && hx < WDIM);
                const __nv_bfloat16* src = gbase +
                    (ok ? ((size_t)(hy * WDIM + hx) * 1024 + cbase + ch * 8) : 0);
                CP_ASYNC16Z(st + row * 512 + ((ch ^ (row & 7)) << 4), src, ok ? 16u : 0u);
            }
            CP_COMMIT();
        };

        issue3(0);
        for (int kk = 0; kk < 4; kk++) {
            CP_WAIT(0);
            __syncthreads();
            if (kk + 1 < 4) issue3(kk + 1);
            const uint32_t st = sbX + (kk & 1) * 32768;
            #pragma unroll
            for (int kh = 0; kh < 4; kh++) {
                uint32_t af[2][4], bm[4][4];
                const int chunk = kk * 8 + kh * 2 + cs;
                #pragma unroll
                for (int mi = 0; mi < 2; mi++)
                    LDSM4(af[mi], sbPW + (warp_m * 32 + mi * 16 + rl) * 528 + chunk * 16);
                const int r = kh * 16 + rl;
                #pragma unroll
                for (int nf = 0; nf < 4; nf++) {
                    const int c16 = warp_n * 8 + nf * 2 + cs;
                    LDSM4T(bm[nf], st + r * 512 + ((c16 ^ (r & 7)) << 4));
                }
                #pragma unroll
                for (int mi = 0; mi < 2; mi++)
                    #pragma unroll
                    for (int nf = 0; nf < 4; nf++) {
                        MMA16816(acc[mi][2 * nf + 0], af[mi], bm[nf][0], bm[nf][1]);
                        MMA16816(acc[mi][2 * nf + 1], af[mi], bm[nf][2], bm[nf][3]);
                    }
            }
        }

        #pragma unroll
        for (int mi = 0; mi < 2; mi++)
            #pragma unroll
            for (int ni = 0; ni < 8; ni++) {
                const int r0 = warp_m * 32 + mi * 16 + (lane >> 2);
                const int cc = cbase + warp_n * 64 + ni * 8 + 2 * (lane & 3);
                #pragma unroll
                for (int hh = 0; hh < 2; hh++) {
                    const int px = r0 + hh * 8;
                    const float is = invs[px];
                    const size_t addr =
                        ((size_t)n * PIX + (h0 + (px >> 3)) * WDIM + (w0 + (px & 7))) * CINT + cc;
                    __nv_bfloat162 pk = __floats2bfloat162_rn(acc[mi][ni][2 * hh + 0] * is,
                                                              acc[mi][ni][2 * hh + 1] * is);
                    *(__nv_bfloat162*)(y + addr) = pk;
                }
            }
        __syncthreads();
    }
}

// ---------------------------------------------------------------------------
extern "C" void kernel_launch(void* const* d_in, const int* in_sizes, int n_in,
                              void* d_out, int out_size)
{
    (void)in_sizes; (void)n_in; (void)out_size;
    const float* x       = (const float*)d_in[0];
    const float* x_ref   = (const float*)d_in[1];
    const float* w_g     = (const float*)d_in[2];
    const float* b_g     = (const float*)d_in[3];
    const float* w_theta = (const float*)d_in[4];
    const float* b_theta = (const float*)d_in[5];
    const float* w_phi   = (const float*)d_in[6];
    const float* b_phi   = (const float*)d_in[7];
    const float* w_out   = (const float*)d_in[8];
    const float* b_out   = (const float*)d_in[9];
    float* out = (float*)d_out;

    __nv_bfloat16 *xT_d, *xrT_d, *thb_d, *gphib_d, *ybf_d, *wth_d, *wgp_d, *wo_d;
    cudaGetSymbolAddress((void**)&xT_d,    g_xT);
    cudaGetSymbolAddress((void**)&xrT_d,   g_xrT);
    cudaGetSymbolAddress((void**)&thb_d,   g_thb);
    cudaGetSymbolAddress((void**)&gphib_d, g_gphib);
    cudaGetSymbolAddress((void**)&ybf_d,   g_ybf);
    cudaGetSymbolAddress((void**)&wth_d,   g_wth);
    cudaGetSymbolAddress((void**)&wgp_d,   g_wgp);
    cudaGetSymbolAddress((void**)&wo_d,    g_wo);

    const int FUSED_SMEM = 33792 + 81920 + 256;   // 115968 (2 CTAs/SM)
    const int GEMM_SMEM  = 2 * 32768;             // 65536
    cudaFuncSetAttribute(fused_attn_k, cudaFuncAttributeMaxDynamicSharedMemorySize, FUSED_SMEM);
    cudaFuncSetAttribute(proj_gemm,   cudaFuncAttributeMaxDynamicSharedMemorySize, GEMM_SMEM);
    cudaFuncSetAttribute(final_gemm,  cudaFuncAttributeMaxDynamicSharedMemorySize, GEMM_SMEM);

    // 1: all weight conversions in one launch
    cvt4_k<<<8192, 256>>>(w_theta, w_g, w_phi, w_out,
                          wth_d, wgp_d, wgp_d + (size_t)CINT * CINF, wo_d);

    // 2: transpose+convert both inputs NCHW fp32 -> [p][1024] bf16
    conv_tr2_k<<<dim3(PIX / 32, CINF / 64, 2 * NB), dim3(32, 8)>>>(x, x_ref, xT_d, xrT_d);

    // 3: merged theta + (g;phi) projections -> bf16 NHWC
    proj_gemm<<<dim3(72, 12, NB), 256, GEMM_SMEM>>>(
        wth_d, wgp_d, xT_d, xrT_d, b_theta, b_g, b_phi, thb_d, gphib_d);

    // 4: fused corr + softmax + assemble -> y bf16 [p][512]
    fused_attn_k<<<dim3(12, 12, NB), 256, FUSED_SMEM>>>(thb_d, gphib_d, ybf_d);

    // 5: out = x + w_out @ y + b_out (fp32 NCHW)
    final_gemm<<<dim3(72, 8, NB), 256, GEMM_SMEM>>>(wo_d, ybf_d, b_out, out, x);
}

// round 12
// speedup vs baseline: 1.0480x; 1.0480x over previous
#include <cuda_runtime.h>
#include <cuda_bf16.h>
#include <cstdint>
#include <math.h>

#define HDIM 96
#define WDIM 96
#define PIX  (HDIM*WDIM)     // 9216
#define NB   4
#define CINF 1024
#define CINT 512
#define DD   4
#define QD   9
#define QQ   81
#define NPIX (NB*PIX)        // 36864

// ------------------------- scratch (device globals) -------------------------
__device__ __nv_bfloat16 g_xT  [(size_t)NPIX * CINF];      // bf16 [p][1024]
__device__ __nv_bfloat16 g_xrT [(size_t)NPIX * CINF];      // bf16 [p][1024]
__device__ __nv_bfloat16 g_thb [(size_t)NPIX * CINT];      // bf16 theta NHWC [p][512]
__device__ __nv_bfloat16 g_gphib[(size_t)NPIX * 2 * CINT]; // bf16 g|phi NHWC [p][1024]
__device__ __nv_bfloat16 g_ybf [(size_t)NPIX * CINT];      // bf16 y NHWC [p][512]
__device__ __nv_bfloat16 g_wth [(size_t)CINT * CINF];
__device__ __nv_bfloat16 g_wgp [(size_t)CINF * CINF];      // (wg;wphi)
__device__ __nv_bfloat16 g_wo  [(size_t)CINF * CINT];

// ------------------------- helpers ------------------------------------------
__device__ __forceinline__ uint32_t smem_u32(const void* p) {
    uint32_t a;
    asm("{ .reg .u64 t; cvta.to.shared.u64 t, %1; cvt.u32.u64 %0, t; }" : "=r"(a) : "l"(p));
    return a;
}
#define CP_ASYNC16(dst, src) \
    asm volatile("cp.async.cg.shared.global [%0], [%1], 16;" :: "r"(dst), "l"(src))
#define CP_ASYNC16Z(dst, src, sz) \
    asm volatile("cp.async.cg.shared.global [%0], [%1], 16, %2;" :: "r"(dst), "l"(src), "r"(sz))
#define CP_COMMIT() asm volatile("cp.async.commit_group;" ::: "memory")
#define CP_WAIT(n)  asm volatile("cp.async.wait_group %0;" :: "n"(n) : "memory")

#define LDSM4(r, a) \
    asm volatile("ldmatrix.sync.aligned.m8n8.x4.shared.b16 {%0,%1,%2,%3}, [%4];" \
        : "=r"((r)[0]), "=r"((r)[1]), "=r"((r)[2]), "=r"((r)[3]) : "r"(a))
#define LDSM4T(r, a) \
    asm volatile("ldmatrix.sync.aligned.m8n8.x4.trans.shared.b16 {%0,%1,%2,%3}, [%4];" \
        : "=r"((r)[0]), "=r"((r)[1]), "=r"((r)[2]), "=r"((r)[3]) : "r"(a))

#define MMA16816(d, a, bb0, bb1) \
    asm volatile("mma.sync.aligned.m16n8k16.row.col.f32.bf16.bf16.f32 " \
        "{%0,%1,%2,%3},{%4,%5,%6,%7},{%8,%9},{%0,%1,%2,%3};" \
        : "+f"((d)[0]), "+f"((d)[1]), "+f"((d)[2]), "+f"((d)[3]) \
        : "r"((a)[0]), "r"((a)[1]), "r"((a)[2]), "r"((a)[3]), "r"(bb0), "r"(bb1))

// 32-bf16-wide tile swizzle (64B rows) — fused kernel phase 1
__device__ __forceinline__ uint32_t sw_off(int row, int ch) {
    return (uint32_t)(row * 64 + ((ch ^ ((row >> 1) & 3)) << 4));
}
// 64-bf16-wide tile swizzle (128B rows) — GEMM stages
__device__ __forceinline__ uint32_t sw128(int row, int ch) {
    return (uint32_t)(row * 128 + ((ch ^ (row & 7)) << 4));
}

// ------------------------- transpose + convert (x & x_ref merged) ------------
__global__ void conv_tr2_k(const float* __restrict__ x, const float* __restrict__ xr,
                           __nv_bfloat16* __restrict__ dx, __nv_bfloat16* __restrict__ dxr)
{
    __shared__ float ts[64][33];
    const int tx = threadIdx.x, ty = threadIdx.y;
    const int z = blockIdx.z;
    const int n = z & (NB - 1);
    const float* src = (z < NB) ? x : xr;
    __nv_bfloat16* dst = (z < NB) ? dx : dxr;
    const int p0 = blockIdx.x * 32, c0 = blockIdx.y * 64;
    #pragma unroll
    for (int r = 0; r < 8; r++) {
        int cl = ty + r * 8;
        ts[cl][tx] = src[((size_t)n * CINF + c0 + cl) * PIX + p0 + tx];
    }
    __syncthreads();
    #pragma unroll
    for (int r = 0; r < 4; r++) {
        int pl = ty + r * 8;
        __nv_bfloat162 v = __floats2bfloat162_rn(ts[2 * tx][pl], ts[2 * tx + 1][pl]);
        *(__nv_bfloat162*)(dst + ((size_t)n * PIX + p0 + pl) * CINF + c0 + 2 * tx) = v;
    }
}

// all four weight tensors are 524288 elements each
__global__ void cvt4_k(const float* __restrict__ s0, const float* __restrict__ s1,
                       const float* __restrict__ s2, const float* __restrict__ s3,
                       __nv_bfloat16* __restrict__ d0, __nv_bfloat16* __restrict__ d1,
                       __nv_bfloat16* __restrict__ d2, __nv_bfloat16* __restrict__ d3)
{
    int i = blockIdx.x * 256 + threadIdx.x;
    int seg = i >> 19, off = i & 524287;
    const float* s = (seg == 0) ? s0 : (seg == 1) ? s1 : (seg == 2) ? s2 : s3;
    __nv_bfloat16* d = (seg == 0) ? d0 : (seg == 1) ? d1 : (seg == 2) ? d2 : d3;
    d[off] = __float2bfloat16(s[off]);
}

// ------------------------- merged projection GEMM ----------------------------
// 128x128 tile, K-chunk 64, 3-stage cp.async (96KB dyn smem), 8 warps, 2 CTA/SM.
__global__ __launch_bounds__(256, 2)
void proj_gemm(const __nv_bfloat16* __restrict__ wth, const __nv_bfloat16* __restrict__ wgp,
               const __nv_bfloat16* __restrict__ xT, const __nv_bfloat16* __restrict__ xrT,
               const float* __restrict__ bth, const float* __restrict__ bg,
               const float* __restrict__ bphi,
               __nv_bfloat16* __restrict__ thb, __nv_bfloat16* __restrict__ gphib)
{
    extern __shared__ char smem[];   // 3 stages x (A 16KB | B 16KB)

    const int t = threadIdx.x, lane = t & 31, wid = t >> 5;
    const int warp_m = wid >> 2, warp_n = wid & 3;
    const int n = blockIdx.z, pbase = blockIdx.x * 128;
    const int by = blockIdx.y;
    const bool th = (by < 4);
    const int obase = (th ? by : by - 4) * 128;
    const __nv_bfloat16* A  = th ? wth : wgp;
    const __nv_bfloat16* Bx = th ? xT : xrT;
    __nv_bfloat16* out = th ? thb : gphib;
    const int ldo = th ? CINT : 2 * CINT;
    const float* b0 = th ? bth : bg;
    const float* b1 = th ? bth : bphi;
    const int K = CINF, NC = K >> 6;   // 16

    const __nv_bfloat16* Ab = A + (size_t)obase * K;
    const __nv_bfloat16* Bb = Bx + ((size_t)n * PIX + pbase) * K;
    const uint32_t sbase = smem_u32(smem);

    float acc[4][4][4];
    #pragma unroll
    for (int mi = 0; mi < 4; mi++)
        #pragma unroll
        for (int ni = 0; ni < 4; ni++)
            #pragma unroll
            for (int r = 0; r < 4; r++) acc[mi][ni][r] = 0.f;

    const int rowL = t >> 3, chL = t & 7;
    auto issue = [&](int c) {
        const int k0 = c << 6;
        const uint32_t st = sbase + (c % 3) * 32768;
        #pragma unroll
        for (int i = 0; i < 4; i++) {
            int row = rowL + i * 32;
            CP_ASYNC16(st + sw128(row, chL), Ab + (size_t)row * K + k0 + chL * 8);
        }
        #pragma unroll
        for (int i = 0; i < 4; i++) {
            int row = rowL + i * 32;
            CP_ASYNC16(st + 16384 + sw128(row, chL), Bb + (size_t)row * K + k0 + chL * 8);
        }
        CP_COMMIT();
    };

    issue(0); issue(1);
    const int rl = lane & 15, cs = lane >> 4;

    for (int c = 0; c < NC; c++) {
        if (c < NC - 1) CP_WAIT(1); else CP_WAIT(0);
        __syncthreads();
        if (c + 2 < NC) issue(c + 2);

        const uint32_t stA = sbase + (c % 3) * 32768;
        const uint32_t stB = stA + 16384;
        #pragma unroll
        for (int kh = 0; kh < 4; kh++) {
            const int ch = 2 * kh + cs;
            uint32_t af[4][4], bf[2][4];
            #pragma unroll
            for (int mi = 0; mi < 4; mi++)
                LDSM4(af[mi], stA + sw128(warp_m * 64 + mi * 16 + rl, ch));
            #pragma unroll
            for (int g = 0; g < 2; g++)
                LDSM4(bf[g], stB + sw128(warp_n * 32 + g * 16 + rl, ch));
            #pragma unroll
            for (int mi = 0; mi < 4; mi++)
                #pragma unroll
                for (int g = 0; g < 2; g++) {
                    MMA16816(acc[mi][2 * g + 0], af[mi], bf[g][0], bf[g][2]);
                    MMA16816(acc[mi][2 * g + 1], af[mi], bf[g][1], bf[g][3]);
                }
        }
    }

    // epilogue: transpose via SMEM -> coalesced bf16 NHWC rows
    __syncthreads();
    __nv_bfloat16* S = (__nv_bfloat16*)smem;   // [128 p][136 o]
    #pragma unroll
    for (int mi = 0; mi < 4; mi++) {
        #pragma unroll
        for (int h = 0; h < 2; h++) {
            const int ol = warp_m * 64 + mi * 16 + (lane >> 2) + h * 8;
            const int og = obase + ol;
            const float bias = (og < CINT) ? b0[og] : b1[og - CINT];
            #pragma unroll
            for (int ni = 0; ni < 4; ni++) {
                const int pl = warp_n * 32 + ni * 8 + (lane & 3) * 2;
                S[(size_t)pl * 136 + ol]       = __float2bfloat16(acc[mi][ni][2 * h + 0] + bias);
                S[(size_t)(pl + 1) * 136 + ol] = __float2bfloat16(acc[mi][ni][2 * h + 1] + bias);
            }
        }
    }
    __syncthreads();
    #pragma unroll
    for (int s = 0; s < 16; s++) {
        const int pl = s * 8 + wid;
        uint2 v = *(uint2*)&S[(size_t)pl * 136 + lane * 4];
        *(uint2*)(out + ((size_t)n * PIX + pbase + pl) * ldo + obase + lane * 4) = v;
    }
}

// ------------------------- final GEMM (residual, fp32 NCHW) ------------------
__global__ __launch_bounds__(256, 2)
void final_gemm(const __nv_bfloat16* __restrict__ A, const __nv_bfloat16* __restrict__ B,
                const float* __restrict__ b0, float* __restrict__ out,
                const float* __restrict__ resid)
{
    extern __shared__ char smem[];   // 3 stages x 32KB

    const int t = threadIdx.x, lane = t & 31, wid = t >> 5;
    const int warp_m = wid >> 2, warp_n = wid & 3;
    const int n = blockIdx.z, pbase = blockIdx.x * 128, obase = blockIdx.y * 128;
    const int K = CINT, NC = K >> 6;   // 8

    const __nv_bfloat16* Ab = A + (size_t)obase * K;
    const __nv_bfloat16* Bb = B + ((size_t)n * PIX + pbase) * K;
    const uint32_t sbase = smem_u32(smem);

    float acc[4][4][4];
    #pragma unroll
    for (int mi = 0; mi < 4; mi++)
        #pragma unroll
        for (int ni = 0; ni < 4; ni++)
            #pragma unroll
            for (int r = 0; r < 4; r++) acc[mi][ni][r] = 0.f;

    const int rowL = t >> 3, chL = t & 7;
    auto issue = [&](int c) {
        const int k0 = c << 6;
        const uint32_t st = sbase + (c % 3) * 32768;
        #pragma unroll
        for (int i = 0; i < 4; i++) {
            int row = rowL + i * 32;
            CP_ASYNC16(st + sw128(row, chL), Ab + (size_t)row * K + k0 + chL * 8);
        }
        #pragma unroll
        for (int i = 0; i < 4; i++) {
            int row = rowL + i * 32;
            CP_ASYNC16(st + 16384 + sw128(row, chL), Bb + (size_t)row * K + k0 + chL * 8);
        }
        CP_COMMIT();
    };

    issue(0); issue(1);
    const int rl = lane & 15, cs = lane >> 4;

    for (int c = 0; c < NC; c++) {
        if (c < NC - 1) CP_WAIT(1); else CP_WAIT(0);
        __syncthreads();
        if (c + 2 < NC) issue(c + 2);

        const uint32_t stA = sbase + (c % 3) * 32768;
        const uint32_t stB = stA + 16384;
        #pragma unroll
        for (int kh = 0; kh < 4; kh++) {
            const int ch = 2 * kh + cs;
            uint32_t af[4][4], bf[2][4];
            #pragma unroll
            for (int mi = 0; mi < 4; mi++)
                LDSM4(af[mi], stA + sw128(warp_m * 64 + mi * 16 + rl, ch));
            #pragma unroll
            for (int g = 0; g < 2; g++)
                LDSM4(bf[g], stB + sw128(warp_n * 32 + g * 16 + rl, ch));
            #pragma unroll
            for (int mi = 0; mi < 4; mi++)
                #pragma unroll
                for (int g = 0; g < 2; g++) {
                    MMA16816(acc[mi][2 * g + 0], af[mi], bf[g][0], bf[g][2]);
                    MMA16816(acc[mi][2 * g + 1], af[mi], bf[g][1], bf[g][3]);
                }
        }
    }

    // epilogue: stage to SMEM, then fully-coalesced resid add + store
    float* Es = (float*)smem;   // [64 o][132 p]
    #pragma unroll
    for (int og = 0; og < 2; og++) {
        __syncthreads();
        if (warp_m == og) {
            #pragma unroll
            for (int mi = 0; mi < 4; mi++)
                #pragma unroll
                for (int h = 0; h < 2; h++) {
                    const int row = mi * 16 + (lane >> 2) + h * 8;
                    #pragma unroll
                    for (int ni = 0; ni < 4; ni++) {
                        const int col = warp_n * 32 + ni * 8 + (lane & 3) * 2;
                        Es[(size_t)row * 132 + col]     = acc[mi][ni][2 * h + 0];
                        Es[(size_t)row * 132 + col + 1] = acc[mi][ni][2 * h + 1];
                    }
                }
        }
        __syncthreads();
        #pragma unroll
        for (int s = 0; s < 8; s++) {
            const int row = s * 8 + wid;
            const int o = obase + og * 64 + row;
            const size_t addr = ((size_t)n * CINF + o) * PIX + pbase + lane * 4;
            float4 e = *(float4*)&Es[(size_t)row * 132 + lane * 4];
            float4 r = *(const float4*)(resid + addr);
            const float bias = b0[o];
            float4 v;
            v.x = e.x + bias + r.x; v.y = e.y + bias + r.y;
            v.z = e.z + bias + r.z; v.w = e.w + bias + r.w;
            *(float4*)(out + addr) = v;
        }
    }
}

// ------------------------- fused corr + softmax + assemble -------------------
// (byte-exact revert to the R10 85us version)
__global__ __launch_bounds__(256, 2)
void fused_attn_k(const __nv_bfloat16* __restrict__ theta,
                  const __nv_bfloat16* __restrict__ gphi,
                  __nv_bfloat16* __restrict__ y)
{
    extern __shared__ char smem[];
    char*  Xr   = smem + 33792;
    float* Cs   = (float*)Xr;                       // [64][266] fp32
    float* invs = (float*)(smem + 33792 + 68096);   // [64]

    const int t = threadIdx.x, lane = t & 31, wid = t >> 5;
    const int warp_m = wid >> 2, warp_n = wid & 3;  // 2 x 4
    const int rl = lane & 15, cs = lane >> 4;
    const int n = blockIdx.z, h0 = blockIdx.y * 8, w0 = blockIdx.x * 8;

    const uint32_t sbX  = smem_u32(Xr);
    const uint32_t sbPW = smem_u32(smem);

    float acc[2][8][4];
    #pragma unroll
    for (int a = 0; a < 2; a++)
        #pragma unroll
        for (int b = 0; b < 8; b++)
            #pragma unroll
            for (int c = 0; c < 4; c++) acc[a][b][c] = 0.f;

    // ---------------- phase 1: corr GEMM ----------------
    const int rowA = t >> 2, chA = t & 3;
    const __nv_bfloat16* thsrc =
        theta + ((size_t)n * PIX + (h0 + (rowA >> 3)) * WDIM + (w0 + (rowA & 7))) * CINT + chA * 8;

    const __nv_bfloat16* phsrc[4];
    uint32_t phok[4]; int phrow[4], phch[4];
    #pragma unroll
    for (int i = 0; i < 4; i++) {
        int idx = t + i * 256;
        int row = idx >> 2, ch = idx & 3;
        int hy = h0 + (row >> 4) - DD, hx = w0 + (row & 15) - DD;
        bool ok = (hy >= 0 && hy < HDIM && hx >= 0 && hx < WDIM);
        phrow[i] = row; phch[i] = ch; phok[i] = ok ? 16u : 0u;
        phsrc[i] = gphi + (ok ? (((size_t)n * PIX + hy * WDIM + hx) * 1024 + 512 + ch * 8) : 0);
    }

    auto issue1 = [&](int c) {
        const int c0 = c << 5;
        const uint32_t st = sbX + (c % 3) * 20480;
        CP_ASYNC16(st + sw_off(rowA, chA), thsrc + c0);
        #pragma unroll
        for (int i = 0; i < 4; i++)
            CP_ASYNC16Z(st + 4096 + sw_off(phrow[i], phch[i]),
                        phsrc[i] + (phok[i] ? c0 : 0), phok[i]);
        CP_COMMIT();
    };

    issue1(0); issue1(1);
    for (int c = 0; c < 16; c++) {
        if (c < 15) CP_WAIT(1); else CP_WAIT(0);
        __syncthreads();
        if (c + 2 < 16) issue1(c + 2);
        const uint32_t stA = sbX + (c % 3) * 20480;
        const uint32_t stB = stA + 4096;
        #pragma unroll
        for (int kh = 0; kh < 2; kh++) {
            const int ch = 2 * kh + cs;
            uint32_t af[2][4], bm[4][4];
            #pragma unroll
            for (int mi = 0; mi < 2; mi++)
                LDSM4(af[mi], stA + sw_off(warp_m * 32 + mi * 16 + rl, ch));
            #pragma unroll
            for (int nf = 0; nf < 4; nf++)
                LDSM4(bm[nf], stB + sw_off(warp_n * 64 + nf * 16 + rl, ch));
            #pragma unroll
            for (int mi = 0; mi < 2; mi++)
                #pragma unroll
                for (int nf = 0; nf < 4; nf++) {
                    MMA16816(acc[mi][2 * nf + 0], af[mi], bm[nf][0], bm[nf][2]);
                    MMA16816(acc[mi][2 * nf + 1], af[mi], bm[nf][1], bm[nf][3]);
                }
        }
    }
    __syncthreads();   // stages dead; write C to smem (overlays stage region)

    #pragma unroll
    for (int mi = 0; mi < 2; mi++)
        #pragma unroll
        for (int ni = 0; ni < 8; ni++) {
            const int r0  = warp_m * 32 + mi * 16 + (lane >> 2);
            const int col = warp_n * 64 + ni * 8 + 2 * (lane & 3);
            *(float2*)&Cs[(size_t)r0 * 266 + col]       = make_float2(acc[mi][ni][0], acc[mi][ni][1]);
            *(float2*)&Cs[(size_t)(r0 + 8) * 266 + col] = make_float2(acc[mi][ni][2], acc[mi][ni][3]);
        }
    __syncthreads();

    // ---------------- phase 2: softmax -> PW bf16 ----------------
    if (t < 64) {
        const int py = t >> 3, pxx = t & 7;
        uint32_t* pwz = (uint32_t*)(smem + t * 528);
        #pragma unroll 4
        for (int i = 0; i < 132; i++) pwz[i] = 0;
        const float SC = 0.051031036307982884f;   // 256/(512*sqrt(96))
        float m = -1e30f;
        #pragma unroll
        for (int dy = 0; dy < QD; dy++)
            #pragma unroll
            for (int dx = 0; dx < QD; dx++)
                m = fmaxf(m, Cs[(size_t)t * 266 + (py + dy) * 16 + pxx + dx] * SC);
        float s = 0.f;
        __nv_bfloat16* pwrow = (__nv_bfloat16*)(smem + t * 528);
        #pragma unroll
        for (int dy = 0; dy < QD; dy++)
            #pragma unroll
            for (int dx = 0; dx < QD; dx++) {
                const int col = (py + dy) * 16 + pxx + dx;
                float e = __expf(Cs[(size_t)t * 266 + col] * SC - m);
                s += e;
                pwrow[col] = __float2bfloat16(e);
            }
        invs[t] = 1.f / s;
    }
    __syncthreads();

    // ---------------- phase 3: assemble GEMM ----------------
    for (int half = 0; half < 2; half++) {
        const int cbase = half * 256;
        #pragma unroll
        for (int a = 0; a < 2; a++)
            #pragma unroll
            for (int b = 0; b < 8; b++)
                #pragma unroll
                for (int c = 0; c < 4; c++) acc[a][b][c] = 0.f;

        auto issue3 = [&](int kk) {
            const uint32_t st = sbX + (kk % 3) * 16384;
            #pragma unroll
            for (int i = 0; i < 4; i++) {
                int idx = t + i * 256;
                int row = idx >> 5, ch = idx & 31;
                int hp = kk * 32 + row;
                int hy = h0 + (hp >> 4) - DD, hx = w0 + (hp & 15) - DD;
                bool ok = (hy >= 0 && hy < HDIM && hx >= 0 && hx < WDIM);
                const __nv_bfloat16* src = gphi +
                    (ok ? (((size_t)n * PIX + hy * WDIM + hx) * 1024 + cbase + ch * 8) : 0);
                CP_ASYNC16Z(st + row * 512 + ((ch ^ (row & 7)) << 4), src, ok ? 16u : 0u);
            }
            CP_COMMIT();
        };

        issue3(0); issue3(1);
        for (int kk = 0; kk < 8; kk++) {
            if (kk < 7) CP_WAIT(1); else CP_WAIT(0);
            __syncthreads();
            if (kk + 2 < 8) issue3(kk + 2);
            const uint32_t st = sbX + (kk % 3) * 16384;
            #pragma unroll
            for (int kh = 0; kh < 2; kh++) {
                uint32_t af[2][4], bm[4][4];
                const int chunk = kk * 4 + kh * 2 + cs;
                #pragma unroll
                for (int mi = 0; mi < 2; mi++)
                    LDSM4(af[mi], sbPW + (warp_m * 32 + mi * 16 + rl) * 528 + chunk * 16);
                const int r = kh * 16 + rl;
                #pragma unroll
                for (int nf = 0; nf < 4; nf++) {
                    const int c16 = warp_n * 8 + nf * 2 + cs;
                    LDSM4T(bm[nf], st + r * 512 + ((c16 ^ (r & 7)) << 4));
                }
                #pragma unroll
                for (int mi = 0; mi < 2; mi++)
                    #pragma unroll
                    for (int nf = 0; nf < 4; nf++) {
                        MMA16816(acc[mi][2 * nf + 0], af[mi], bm[nf][0], bm[nf][1]);
                        MMA16816(acc[mi][2 * nf + 1], af[mi], bm[nf][2], bm[nf][3]);
                    }
            }
        }

        #pragma unroll
        for (int mi = 0; mi < 2; mi++)
            #pragma unroll
            for (int ni = 0; ni < 8; ni++) {
                const int r0 = warp_m * 32 + mi * 16 + (lane >> 2);
                const int cc = cbase + warp_n * 64 + ni * 8 + 2 * (lane & 3);
                #pragma unroll
                for (int hh = 0; hh < 2; hh++) {
                    const int px = r0 + hh * 8;
                    const float is = invs[px];
                    const size_t addr =
                        ((size_t)n * PIX + (h0 + (px >> 3)) * WDIM + (w0 + (px & 7))) * CINT + cc;
                    __nv_bfloat162 pk = __floats2bfloat162_rn(acc[mi][ni][2 * hh + 0] * is,
                                                              acc[mi][ni][2 * hh + 1] * is);
                    *(__nv_bfloat162*)(y + addr) = pk;
                }
            }
        __syncthreads();
    }
}

// ---------------------------------------------------------------------------
extern "C" void kernel_launch(void* const* d_in, const int* in_sizes, int n_in,
                              void* d_out, int out_size)
{
    (void)in_sizes; (void)n_in; (void)out_size;
    const float* x       = (const float*)d_in[0];
    const float* x_ref   = (const float*)d_in[1];
    const float* w_g     = (const float*)d_in[2];
    const float* b_g     = (const float*)d_in[3];
    const float* w_theta = (const float*)d_in[4];
    const float* b_theta = (const float*)d_in[5];
    const float* w_phi   = (const float*)d_in[6];
    const float* b_phi   = (const float*)d_in[7];
    const float* w_out   = (const float*)d_in[8];
    const float* b_out   = (const float*)d_in[9];
    float* out = (float*)d_out;

    __nv_bfloat16 *xT_d, *xrT_d, *thb_d, *gphib_d, *ybf_d, *wth_d, *wgp_d, *wo_d;
    cudaGetSymbolAddress((void**)&xT_d,    g_xT);
    cudaGetSymbolAddress((void**)&xrT_d,   g_xrT);
    cudaGetSymbolAddress((void**)&thb_d,   g_thb);
    cudaGetSymbolAddress((void**)&gphib_d, g_gphib);
    cudaGetSymbolAddress((void**)&ybf_d,   g_ybf);
    cudaGetSymbolAddress((void**)&wth_d,   g_wth);
    cudaGetSymbolAddress((void**)&wgp_d,   g_wgp);
    cudaGetSymbolAddress((void**)&wo_d,    g_wo);

    const int FUSED_SMEM = 33792 + 68096 + 256;   // 102144 (2 CTAs/SM)
    const int GEMM_SMEM  = 3 * 32768;             // 98304  (2 CTAs/SM)
    cudaFuncSetAttribute(fused_attn_k, cudaFuncAttributeMaxDynamicSharedMemorySize, FUSED_SMEM);
    cudaFuncSetAttribute(proj_gemm,   cudaFuncAttributeMaxDynamicSharedMemorySize, GEMM_SMEM);
    cudaFuncSetAttribute(final_gemm,  cudaFuncAttributeMaxDynamicSharedMemorySize, GEMM_SMEM);

    // 1: all weight conversions in one launch
    cvt4_k<<<8192, 256>>>(w_theta, w_g, w_phi, w_out,
                          wth_d, wgp_d, wgp_d + (size_t)CINT * CINF, wo_d);

    // 2: transpose+convert both inputs NCHW fp32 -> [p][1024] bf16
    conv_tr2_k<<<dim3(PIX / 32, CINF / 64, 2 * NB), dim3(32, 8)>>>(x, x_ref, xT_d, xrT_d);

    // 3: merged theta + (g;phi) projections -> bf16 NHWC
    proj_gemm<<<dim3(72, 12, NB), 256, GEMM_SMEM>>>(
        wth_d, wgp_d, xT_d, xrT_d, b_theta, b_g, b_phi, thb_d, gphib_d);

    // 4: fused corr + softmax + assemble -> y bf16 [p][512]
    fused_attn_k<<<dim3(12, 12, NB), 256, FUSED_SMEM>>>(thb_d, gphib_d, ybf_d);

    // 5: out = x + w_out @ y + b_out (fp32 NCHW)
    final_gemm<<<dim3(72, 8, NB), 256, GEMM_SMEM>>>(wo_d, ybf_d, b_out, out, x);
}

// round 14
// speedup vs baseline: 1.0508x; 1.0027x over previous
#include <cuda_runtime.h>
#include <cuda_bf16.h>
#include <cstdint>
#include <math.h>

#define HDIM 96
#define WDIM 96
#define PIX  (HDIM*WDIM)     // 9216
#define NB   4
#define CINF 1024
#define CINT 512
#define DD   4
#define QD   9
#define QQ   81
#define NPIX (NB*PIX)        // 36864

// ------------------------- scratch (device globals) -------------------------
__device__ __nv_bfloat16 g_xT  [(size_t)NPIX * CINF];      // bf16 [p][1024]
__device__ __nv_bfloat16 g_xrT [(size_t)NPIX * CINF];      // bf16 [p][1024]
__device__ __nv_bfloat16 g_thb [(size_t)NPIX * CINT];      // bf16 theta NHWC [p][512]
__device__ __nv_bfloat16 g_gphib[(size_t)NPIX * 2 * CINT]; // bf16 g|phi NHWC [p][1024]
__device__ __nv_bfloat16 g_ybf [(size_t)NPIX * CINT];      // bf16 y NHWC [p][512]
__device__ __nv_bfloat16 g_wth [(size_t)CINT * CINF];
__device__ __nv_bfloat16 g_wgp [(size_t)CINF * CINF];      // (wg;wphi)
__device__ __nv_bfloat16 g_wo  [(size_t)CINF * CINT];

// ------------------------- helpers ------------------------------------------
__device__ __forceinline__ uint32_t smem_u32(const void* p) {
    uint32_t a;
    asm("{ .reg .u64 t; cvta.to.shared.u64 t, %1; cvt.u32.u64 %0, t; }" : "=r"(a) : "l"(p));
    return a;
}
#define CP_ASYNC16(dst, src) \
    asm volatile("cp.async.cg.shared.global [%0], [%1], 16;" :: "r"(dst), "l"(src))
#define CP_ASYNC16Z(dst, src, sz) \
    asm volatile("cp.async.cg.shared.global [%0], [%1], 16, %2;" :: "r"(dst), "l"(src), "r"(sz))
#define CP_COMMIT() asm volatile("cp.async.commit_group;" ::: "memory")
#define CP_WAIT(n)  asm volatile("cp.async.wait_group %0;" :: "n"(n) : "memory")

#define LDSM4(r, a) \
    asm volatile("ldmatrix.sync.aligned.m8n8.x4.shared.b16 {%0,%1,%2,%3}, [%4];" \
        : "=r"((r)[0]), "=r"((r)[1]), "=r"((r)[2]), "=r"((r)[3]) : "r"(a))
#define LDSM4T(r, a) \
    asm volatile("ldmatrix.sync.aligned.m8n8.x4.trans.shared.b16 {%0,%1,%2,%3}, [%4];" \
        : "=r"((r)[0]), "=r"((r)[1]), "=r"((r)[2]), "=r"((r)[3]) : "r"(a))

#define MMA16816(d, a, bb0, bb1) \
    asm volatile("mma.sync.aligned.m16n8k16.row.col.f32.bf16.bf16.f32 " \
        "{%0,%1,%2,%3},{%4,%5,%6,%7},{%8,%9},{%0,%1,%2,%3};" \
        : "+f"((d)[0]), "+f"((d)[1]), "+f"((d)[2]), "+f"((d)[3]) \
        : "r"((a)[0]), "r"((a)[1]), "r"((a)[2]), "r"((a)[3]), "r"(bb0), "r"(bb1))

// 32-bf16-wide tile swizzle (64B rows) — fused kernel phase 1
__device__ __forceinline__ uint32_t sw_off(int row, int ch) {
    return (uint32_t)(row * 64 + ((ch ^ ((row >> 1) & 3)) << 4));
}
// 64-bf16-wide tile swizzle (128B rows) — GEMM stages
__device__ __forceinline__ uint32_t sw128(int row, int ch) {
    return (uint32_t)(row * 128 + ((ch ^ (row & 7)) << 4));
}

// ------------------------- transpose + convert (x & x_ref merged) ------------
__global__ void conv_tr2_k(const float* __restrict__ x, const float* __restrict__ xr,
                           __nv_bfloat16* __restrict__ dx, __nv_bfloat16* __restrict__ dxr)
{
    __shared__ float ts[64][33];
    const int tx = threadIdx.x, ty = threadIdx.y;
    const int z = blockIdx.z;
    const int n = z & (NB - 1);
    const float* src = (z < NB) ? x : xr;
    __nv_bfloat16* dst = (z < NB) ? dx : dxr;
    const int p0 = blockIdx.x * 32, c0 = blockIdx.y * 64;
    #pragma unroll
    for (int r = 0; r < 8; r++) {
        int cl = ty + r * 8;
        ts[cl][tx] = src[((size_t)n * CINF + c0 + cl) * PIX + p0 + tx];
    }
    __syncthreads();
    #pragma unroll
    for (int r = 0; r < 4; r++) {
        int pl = ty + r * 8;
        __nv_bfloat162 v = __floats2bfloat162_rn(ts[2 * tx][pl], ts[2 * tx + 1][pl]);
        *(__nv_bfloat162*)(dst + ((size_t)n * PIX + p0 + pl) * CINF + c0 + 2 * tx) = v;
    }
}

// all four weight tensors are 524288 elements each
__global__ void cvt4_k(const float* __restrict__ s0, const float* __restrict__ s1,
                       const float* __restrict__ s2, const float* __restrict__ s3,
                       __nv_bfloat16* __restrict__ d0, __nv_bfloat16* __restrict__ d1,
                       __nv_bfloat16* __restrict__ d2, __nv_bfloat16* __restrict__ d3)
{
    int i = blockIdx.x * 256 + threadIdx.x;
    int seg = i >> 19, off = i & 524287;
    const float* s = (seg == 0) ? s0 : (seg == 1) ? s1 : (seg == 2) ? s2 : s3;
    __nv_bfloat16* d = (seg == 0) ? d0 : (seg == 1) ? d1 : (seg == 2) ? d2 : d3;
    d[off] = __float2bfloat16(s[off]);
}

// ------------------------- merged projection GEMM ----------------------------
// blockIdx.x < 4 : theta = w_theta @ x   -> thb  [p][512]
// blockIdx.x >= 4: (g;phi) = wgp @ x_ref -> gphib [p][1024]
// GRID SWAPPED: output-block index is blockIdx.x (fast) so the 12 CTAs sharing
// one B tile (same pbase) are consecutive -> co-resident -> B served from L2.
// 128x128 tile, K-chunk 64, 2-stage cp.async, 8 warps, 2 CTA/SM.
__global__ __launch_bounds__(256, 2)
void proj_gemm(const __nv_bfloat16* __restrict__ wth, const __nv_bfloat16* __restrict__ wgp,
               const __nv_bfloat16* __restrict__ xT, const __nv_bfloat16* __restrict__ xrT,
               const float* __restrict__ bth, const float* __restrict__ bg,
               const float* __restrict__ bphi,
               __nv_bfloat16* __restrict__ thb, __nv_bfloat16* __restrict__ gphib)
{
    extern __shared__ char smem[];   // 2 stages x (A 16KB | B 16KB)

    const int t = threadIdx.x, lane = t & 31, wid = t >> 5;
    const int warp_m = wid >> 2, warp_n = wid & 3;
    const int n = blockIdx.z, pbase = blockIdx.y * 128;
    const int by = blockIdx.x;
    const bool th = (by < 4);
    const int obase = (th ? by : by - 4) * 128;
    const __nv_bfloat16* A  = th ? wth : wgp;
    const __nv_bfloat16* Bx = th ? xT : xrT;
    __nv_bfloat16* out = th ? thb : gphib;
    const int ldo = th ? CINT : 2 * CINT;
    const float* b0 = th ? bth : bg;
    const float* b1 = th ? bth : bphi;
    const int K = CINF, NC = K >> 6;   // 16

    const __nv_bfloat16* Ab = A + (size_t)obase * K;
    const __nv_bfloat16* Bb = Bx + ((size_t)n * PIX + pbase) * K;
    const uint32_t sbase = smem_u32(smem);

    float acc[4][4][4];
    #pragma unroll
    for (int mi = 0; mi < 4; mi++)
        #pragma unroll
        for (int ni = 0; ni < 4; ni++)
            #pragma unroll
            for (int r = 0; r < 4; r++) acc[mi][ni][r] = 0.f;

    const int rowL = t >> 3, chL = t & 7;
    auto issue = [&](int c) {
        const int k0 = c << 6;
        const uint32_t st = sbase + (c & 1) * 32768;
        #pragma unroll
        for (int i = 0; i < 4; i++) {
            int row = rowL + i * 32;
            CP_ASYNC16(st + sw128(row, chL), Ab + (size_t)row * K + k0 + chL * 8);
        }
        #pragma unroll
        for (int i = 0; i < 4; i++) {
            int row = rowL + i * 32;
            CP_ASYNC16(st + 16384 + sw128(row, chL), Bb + (size_t)row * K + k0 + chL * 8);
        }
        CP_COMMIT();
    };

    issue(0);
    const int rl = lane & 15, cs = lane >> 4;

    for (int c = 0; c < NC; c++) {
        CP_WAIT(0);
        __syncthreads();
        if (c + 1 < NC) issue(c + 1);

        const uint32_t stA = sbase + (c & 1) * 32768;
        const uint32_t stB = stA + 16384;
        #pragma unroll
        for (int kh = 0; kh < 4; kh++) {
            const int ch = 2 * kh + cs;
            uint32_t af[4][4], bf[2][4];
            #pragma unroll
            for (int mi = 0; mi < 4; mi++)
                LDSM4(af[mi], stA + sw128(warp_m * 64 + mi * 16 + rl, ch));
            #pragma unroll
            for (int g = 0; g < 2; g++)
                LDSM4(bf[g], stB + sw128(warp_n * 32 + g * 16 + rl, ch));
            #pragma unroll
            for (int mi = 0; mi < 4; mi++)
                #pragma unroll
                for (int g = 0; g < 2; g++) {
                    MMA16816(acc[mi][2 * g + 0], af[mi], bf[g][0], bf[g][2]);
                    MMA16816(acc[mi][2 * g + 1], af[mi], bf[g][1], bf[g][3]);
                }
        }
    }

    // epilogue: transpose via SMEM -> coalesced bf16 NHWC rows
    __syncthreads();
    __nv_bfloat16* S = (__nv_bfloat16*)smem;   // [128 p][136 o]
    #pragma unroll
    for (int mi = 0; mi < 4; mi++) {
        #pragma unroll
        for (int h = 0; h < 2; h++) {
            const int ol = warp_m * 64 + mi * 16 + (lane >> 2) + h * 8;
            const int og = obase + ol;
            const float bias = (og < CINT) ? b0[og] : b1[og - CINT];
            #pragma unroll
            for (int ni = 0; ni < 4; ni++) {
                const int pl = warp_n * 32 + ni * 8 + (lane & 3) * 2;
                S[(size_t)pl * 136 + ol]       = __float2bfloat16(acc[mi][ni][2 * h + 0] + bias);
                S[(size_t)(pl + 1) * 136 + ol] = __float2bfloat16(acc[mi][ni][2 * h + 1] + bias);
            }
        }
    }
    __syncthreads();
    #pragma unroll
    for (int s = 0; s < 16; s++) {
        const int pl = s * 8 + wid;
        uint2 v = *(uint2*)&S[(size_t)pl * 136 + lane * 4];
        *(uint2*)(out + ((size_t)n * PIX + pbase + pl) * ldo + obase + lane * 4) = v;
    }
}

// ------------------------- final GEMM (residual, fp32 NCHW) ------------------
// GRID SWAPPED: obase fast so the 8 CTAs sharing a y B-tile are consecutive.
__global__ __launch_bounds__(256, 2)
void final_gemm(const __nv_bfloat16* __restrict__ A, const __nv_bfloat16* __restrict__ B,
                const float* __restrict__ b0, float* __restrict__ out,
                const float* __restrict__ resid)
{
    extern __shared__ char smem[];   // 2 stages x 32KB

    const int t = threadIdx.x, lane = t & 31, wid = t >> 5;
    const int warp_m = wid >> 2, warp_n = wid & 3;
    const int n = blockIdx.z, pbase = blockIdx.y * 128, obase = blockIdx.x * 128;
    const int K = CINT, NC = K >> 6;   // 8

    const __nv_bfloat16* Ab = A + (size_t)obase * K;
    const __nv_bfloat16* Bb = B + ((size_t)n * PIX + pbase) * K;
    const uint32_t sbase = smem_u32(smem);

    float acc[4][4][4];
    #pragma unroll
    for (int mi = 0; mi < 4; mi++)
        #pragma unroll
        for (int ni = 0; ni < 4; ni++)
            #pragma unroll
            for (int r = 0; r < 4; r++) acc[mi][ni][r] = 0.f;

    const int rowL = t >> 3, chL = t & 7;
    auto issue = [&](int c) {
        const int k0 = c << 6;
        const uint32_t st = sbase + (c & 1) * 32768;
        #pragma unroll
        for (int i = 0; i < 4; i++) {
            int row = rowL + i * 32;
            CP_ASYNC16(st + sw128(row, chL), Ab + (size_t)row * K + k0 + chL * 8);
        }
        #pragma unroll
        for (int i = 0; i < 4; i++) {
            int row = rowL + i * 32;
            CP_ASYNC16(st + 16384 + sw128(row, chL), Bb + (size_t)row * K + k0 + chL * 8);
        }
        CP_COMMIT();
    };

    issue(0);
    const int rl = lane & 15, cs = lane >> 4;

    for (int c = 0; c < NC; c++) {
        CP_WAIT(0);
        __syncthreads();
        if (c + 1 < NC) issue(c + 1);

        const uint32_t stA = sbase + (c & 1) * 32768;
        const uint32_t stB = stA + 16384;
        #pragma unroll
        for (int kh = 0; kh < 4; kh++) {
            const int ch = 2 * kh + cs;
            uint32_t af[4][4], bf[2][4];
            #pragma unroll
            for (int mi = 0; mi < 4; mi++)
                LDSM4(af[mi], stA + sw128(warp_m * 64 + mi * 16 + rl, ch));
            #pragma unroll
            for (int g = 0; g < 2; g++)
                LDSM4(bf[g], stB + sw128(warp_n * 32 + g * 16 + rl, ch));
            #pragma unroll
            for (int mi = 0; mi < 4; mi++)
                #pragma unroll
                for (int g = 0; g < 2; g++) {
                    MMA16816(acc[mi][2 * g + 0], af[mi], bf[g][0], bf[g][2]);
                    MMA16816(acc[mi][2 * g + 1], af[mi], bf[g][1], bf[g][3]);
                }
        }
    }

    // epilogue: stage to SMEM, then fully-coalesced resid add + store
    float* Es = (float*)smem;   // [64 o][132 p]
    #pragma unroll
    for (int og = 0; og < 2; og++) {
        __syncthreads();
        if (warp_m == og) {
            #pragma unroll
            for (int mi = 0; mi < 4; mi++)
                #pragma unroll
                for (int h = 0; h < 2; h++) {
                    const int row = mi * 16 + (lane >> 2) + h * 8;
                    #pragma unroll
                    for (int ni = 0; ni < 4; ni++) {
                        const int col = warp_n * 32 + ni * 8 + (lane & 3) * 2;
                        Es[(size_t)row * 132 + col]     = acc[mi][ni][2 * h + 0];
                        Es[(size_t)row * 132 + col + 1] = acc[mi][ni][2 * h + 1];
                    }
                }
        }
        __syncthreads();
        #pragma unroll
        for (int s = 0; s < 8; s++) {
            const int row = s * 8 + wid;
            const int o = obase + og * 64 + row;
            const size_t addr = ((size_t)n * CINF + o) * PIX + pbase + lane * 4;
            float4 e = *(float4*)&Es[(size_t)row * 132 + lane * 4];
            float4 r = *(const float4*)(resid + addr);
            const float bias = b0[o];
            float4 v;
            v.x = e.x + bias + r.x; v.y = e.y + bias + r.y;
            v.z = e.z + bias + r.z; v.w = e.w + bias + r.w;
            *(float4*)(out + addr) = v;
        }
    }
}

// ------------------------- fused corr + softmax + assemble -------------------
// (byte-exact R10 85us version)
__global__ __launch_bounds__(256, 2)
void fused_attn_k(const __nv_bfloat16* __restrict__ theta,
                  const __nv_bfloat16* __restrict__ gphi,
                  __nv_bfloat16* __restrict__ y)
{
    extern __shared__ char smem[];
    char*  Xr   = smem + 33792;
    float* Cs   = (float*)Xr;                       // [64][266] fp32
    float* invs = (float*)(smem + 33792 + 68096);   // [64]

    const int t = threadIdx.x, lane = t & 31, wid = t >> 5;
    const int warp_m = wid >> 2, warp_n = wid & 3;  // 2 x 4
    const int rl = lane & 15, cs = lane >> 4;
    const int n = blockIdx.z, h0 = blockIdx.y * 8, w0 = blockIdx.x * 8;

    const uint32_t sbX  = smem_u32(Xr);
    const uint32_t sbPW = smem_u32(smem);

    float acc[2][8][4];
    #pragma unroll
    for (int a = 0; a < 2; a++)
        #pragma unroll
        for (int b = 0; b < 8; b++)
            #pragma unroll
            for (int c = 0; c < 4; c++) acc[a][b][c] = 0.f;

    // ---------------- phase 1: corr GEMM ----------------
    const int rowA = t >> 2, chA = t & 3;
    const __nv_bfloat16* thsrc =
        theta + ((size_t)n * PIX + (h0 + (rowA >> 3)) * WDIM + (w0 + (rowA & 7))) * CINT + chA * 8;

    const __nv_bfloat16* phsrc[4];
    uint32_t phok[4]; int phrow[4], phch[4];
    #pragma unroll
    for (int i = 0; i < 4; i++) {
        int idx = t + i * 256;
        int row = idx >> 2, ch = idx & 3;
        int hy = h0 + (row >> 4) - DD, hx = w0 + (row & 15) - DD;
        bool ok = (hy >= 0 && hy < HDIM && hx >= 0 && hx < WDIM);
        phrow[i] = row; phch[i] = ch; phok[i] = ok ? 16u : 0u;
        phsrc[i] = gphi + (ok ? (((size_t)n * PIX + hy * WDIM + hx) * 1024 + 512 + ch * 8) : 0);
    }

    auto issue1 = [&](int c) {
        const int c0 = c << 5;
        const uint32_t st = sbX + (c % 3) * 20480;
        CP_ASYNC16(st + sw_off(rowA, chA), thsrc + c0);
        #pragma unroll
        for (int i = 0; i < 4; i++)
            CP_ASYNC16Z(st + 4096 + sw_off(phrow[i], phch[i]),
                        phsrc[i] + (phok[i] ? c0 : 0), phok[i]);
        CP_COMMIT();
    };

    issue1(0); issue1(1);
    for (int c = 0; c < 16; c++) {
        if (c < 15) CP_WAIT(1); else CP_WAIT(0);
        __syncthreads();
        if (c + 2 < 16) issue1(c + 2);
        const uint32_t stA = sbX + (c % 3) * 20480;
        const uint32_t stB = stA + 4096;
        #pragma unroll
        for (int kh = 0; kh < 2; kh++) {
            const int ch = 2 * kh + cs;
            uint32_t af[2][4], bm[4][4];
            #pragma unroll
            for (int mi = 0; mi < 2; mi++)
                LDSM4(af[mi], stA + sw_off(warp_m * 32 + mi * 16 + rl, ch));
            #pragma unroll
            for (int nf = 0; nf < 4; nf++)
                LDSM4(bm[nf], stB + sw_off(warp_n * 64 + nf * 16 + rl, ch));
            #pragma unroll
            for (int mi = 0; mi < 2; mi++)
                #pragma unroll
                for (int nf = 0; nf < 4; nf++) {
                    MMA16816(acc[mi][2 * nf + 0], af[mi], bm[nf][0], bm[nf][2]);
                    MMA16816(acc[mi][2 * nf + 1], af[mi], bm[nf][1], bm[nf][3]);
                }
        }
    }
    __syncthreads();   // stages dead; write C to smem (overlays stage region)

    #pragma unroll
    for (int mi = 0; mi < 2; mi++)
        #pragma unroll
        for (int ni = 0; ni < 8; ni++) {
            const int r0  = warp_m * 32 + mi * 16 + (lane >> 2);
            const int col = warp_n * 64 + ni * 8 + 2 * (lane & 3);
            *(float2*)&Cs[(size_t)r0 * 266 + col]       = make_float2(acc[mi][ni][0], acc[mi][ni][1]);
            *(float2*)&Cs[(size_t)(r0 + 8) * 266 + col] = make_float2(acc[mi][ni][2], acc[mi][ni][3]);
        }
    __syncthreads();

    // ---------------- phase 2: softmax -> PW bf16 ----------------
    if (t < 64) {
        const int py = t >> 3, pxx = t & 7;
        uint32_t* pwz = (uint32_t*)(smem + t * 528);
        #pragma unroll 4
        for (int i = 0; i < 132; i++) pwz[i] = 0;
        const float SC = 0.051031036307982884f;   // 256/(512*sqrt(96))
        float m = -1e30f;
        #pragma unroll
        for (int dy = 0; dy < QD; dy++)
            #pragma unroll
            for (int dx = 0; dx < QD; dx++)
                m = fmaxf(m, Cs[(size_t)t * 266 + (py + dy) * 16 + pxx + dx] * SC);
        float s = 0.f;
        __nv_bfloat16* pwrow = (__nv_bfloat16*)(smem + t * 528);
        #pragma unroll
        for (int dy = 0; dy < QD; dy++)
            #pragma unroll
            for (int dx = 0; dx < QD; dx++) {
                const int col = (py + dy) * 16 + pxx + dx;
                float e = __expf(Cs[(size_t)t * 266 + col] * SC - m);
                s += e;
                pwrow[col] = __float2bfloat16(e);
            }
        invs[t] = 1.f / s;
    }
    __syncthreads();

    // ---------------- phase 3: assemble GEMM ----------------
    for (int half = 0; half < 2; half++) {
        const int cbase = half * 256;
        #pragma unroll
        for (int a = 0; a < 2; a++)
            #pragma unroll
            for (int b = 0; b < 8; b++)
                #pragma unroll
                for (int c = 0; c < 4; c++) acc[a][b][c] = 0.f;

        auto issue3 = [&](int kk) {
            const uint32_t st = sbX + (kk % 3) * 16384;
            #pragma unroll
            for (int i = 0; i < 4; i++) {
                int idx = t + i * 256;
                int row = idx >> 5, ch = idx & 31;
                int hp = kk * 32 + row;
                int hy = h0 + (hp >> 4) - DD, hx = w0 + (hp & 15) - DD;
                bool ok = (hy >= 0 && hy < HDIM && hx >= 0 && hx < WDIM);
                const __nv_bfloat16* src = gphi +
                    (ok ? (((size_t)n * PIX + hy * WDIM + hx) * 1024 + cbase + ch * 8) : 0);
                CP_ASYNC16Z(st + row * 512 + ((ch ^ (row & 7)) << 4), src, ok ? 16u : 0u);
            }
            CP_COMMIT();
        };

        issue3(0); issue3(1);
        for (int kk = 0; kk < 8; kk++) {
            if (kk < 7) CP_WAIT(1); else CP_WAIT(0);
            __syncthreads();
            if (kk + 2 < 8) issue3(kk + 2);
            const uint32_t st = sbX + (kk % 3) * 16384;
            #pragma unroll
            for (int kh = 0; kh < 2; kh++) {
                uint32_t af[2][4], bm[4][4];
                const int chunk = kk * 4 + kh * 2 + cs;
                #pragma unroll
                for (int mi = 0; mi < 2; mi++)
                    LDSM4(af[mi], sbPW + (warp_m * 32 + mi * 16 + rl) * 528 + chunk * 16);
                const int r = kh * 16 + rl;
                #pragma unroll
                for (int nf = 0; nf < 4; nf++) {
                    const int c16 = warp_n * 8 + nf * 2 + cs;
                    LDSM4T(bm[nf], st + r * 512 + ((c16 ^ (r & 7)) << 4));
                }
                #pragma unroll
                for (int mi = 0; mi < 2; mi++)
                    #pragma unroll
                    for (int nf = 0; nf < 4; nf++) {
                        MMA16816(acc[mi][2 * nf + 0], af[mi], bm[nf][0], bm[nf][1]);
                        MMA16816(acc[mi][2 * nf + 1], af[mi], bm[nf][2], bm[nf][3]);
                    }
            }
        }

        #pragma unroll
        for (int mi = 0; mi < 2; mi++)
            #pragma unroll
            for (int ni = 0; ni < 8; ni++) {
                const int r0 = warp_m * 32 + mi * 16 + (lane >> 2);
                const int cc = cbase + warp_n * 64 + ni * 8 + 2 * (lane & 3);
                #pragma unroll
                for (int hh = 0; hh < 2; hh++) {
                    const int px = r0 + hh * 8;
                    const float is = invs[px];
                    const size_t addr =
                        ((size_t)n * PIX + (h0 + (px >> 3)) * WDIM + (w0 + (px & 7))) * CINT + cc;
                    __nv_bfloat162 pk = __floats2bfloat162_rn(acc[mi][ni][2 * hh + 0] * is,
                                                              acc[mi][ni][2 * hh + 1] * is);
                    *(__nv_bfloat162*)(y + addr) = pk;
                }
            }
        __syncthreads();
    }
}

// ---------------------------------------------------------------------------
extern "C" void kernel_launch(void* const* d_in, const int* in_sizes, int n_in,
                              void* d_out, int out_size)
{
    (void)in_sizes; (void)n_in; (void)out_size;
    const float* x       = (const float*)d_in[0];
    const float* x_ref   = (const float*)d_in[1];
    const float* w_g     = (const float*)d_in[2];
    const float* b_g     = (const float*)d_in[3];
    const float* w_theta = (const float*)d_in[4];
    const float* b_theta = (const float*)d_in[5];
    const float* w_phi   = (const float*)d_in[6];
    const float* b_phi   = (const float*)d_in[7];
    const float* w_out   = (const float*)d_in[8];
    const float* b_out   = (const float*)d_in[9];
    float* out = (float*)d_out;

    __nv_bfloat16 *xT_d, *xrT_d, *thb_d, *gphib_d, *ybf_d, *wth_d, *wgp_d, *wo_d;
    cudaGetSymbolAddress((void**)&xT_d,    g_xT);
    cudaGetSymbolAddress((void**)&xrT_d,   g_xrT);
    cudaGetSymbolAddress((void**)&thb_d,   g_thb);
    cudaGetSymbolAddress((void**)&gphib_d, g_gphib);
    cudaGetSymbolAddress((void**)&ybf_d,   g_ybf);
    cudaGetSymbolAddress((void**)&wth_d,   g_wth);
    cudaGetSymbolAddress((void**)&wgp_d,   g_wgp);
    cudaGetSymbolAddress((void**)&wo_d,    g_wo);

    const int FUSED_SMEM = 33792 + 68096 + 256;   // 102144 (2 CTAs/SM)
    const int GEMM_SMEM  = 2 * 32768;             // 65536
    cudaFuncSetAttribute(fused_attn_k, cudaFuncAttributeMaxDynamicSharedMemorySize, FUSED_SMEM);
    cudaFuncSetAttribute(proj_gemm,   cudaFuncAttributeMaxDynamicSharedMemorySize, GEMM_SMEM);
    cudaFuncSetAttribute(final_gemm,  cudaFuncAttributeMaxDynamicSharedMemorySize, GEMM_SMEM);

    // 1: all weight conversions in one launch
    cvt4_k<<<8192, 256>>>(w_theta, w_g, w_phi, w_out,
                          wth_d, wgp_d, wgp_d + (size_t)CINT * CINF, wo_d);

    // 2: transpose+convert both inputs NCHW fp32 -> [p][1024] bf16
    conv_tr2_k<<<dim3(PIX / 32, CINF / 64, 2 * NB), dim3(32, 8)>>>(x, x_ref, xT_d, xrT_d);

    // 3: merged theta + (g;phi) projections -> bf16 NHWC  (grid swapped)
    proj_gemm<<<dim3(12, 72, NB), 256, GEMM_SMEM>>>(
        wth_d, wgp_d, xT_d, xrT_d, b_theta, b_g, b_phi, thb_d, gphib_d);

    // 4: fused corr + softmax + assemble -> y bf16 [p][512]
    fused_attn_k<<<dim3(12, 12, NB), 256, FUSED_SMEM>>>(thb_d, gphib_d, ybf_d);

    // 5: out = x + w_out @ y + b_out (fp32 NCHW)  (grid swapped)
    final_gemm<<<dim3(8, 72, NB), 256, GEMM_SMEM>>>(wo_d, ybf_d, b_out, out, x);
}

// round 15
// speedup vs baseline: 1.0748x; 1.0228x over previous
#include <cuda_runtime.h>
#include <cuda_bf16.h>
#include <cstdint>
#include <math.h>

#define HDIM 96
#define WDIM 96
#define PIX  (HDIM*WDIM)     // 9216
#define NB   4
#define CINF 1024
#define CINT 512
#define DD   4
#define QD   9
#define QQ   81
#define NPIX (NB*PIX)        // 36864

// ------------------------- scratch (device globals) -------------------------
__device__ __nv_bfloat16 g_thb [(size_t)NPIX * CINT];      // bf16 theta NHWC [p][512]
__device__ __nv_bfloat16 g_gphib[(size_t)NPIX * 2 * CINT]; // bf16 g|phi NHWC [p][1024]
__device__ __nv_bfloat16 g_ybf [(size_t)NPIX * CINT];      // bf16 y NHWC [p][512]
__device__ __nv_bfloat16 g_wth [(size_t)CINT * CINF];
__device__ __nv_bfloat16 g_wgp [(size_t)CINF * CINF];      // (wg;wphi)
__device__ __nv_bfloat16 g_wo  [(size_t)CINF * CINT];

// ------------------------- helpers ------------------------------------------
__device__ __forceinline__ uint32_t smem_u32(const void* p) {
    uint32_t a;
    asm("{ .reg .u64 t; cvta.to.shared.u64 t, %1; cvt.u32.u64 %0, t; }" : "=r"(a) : "l"(p));
    return a;
}
#define CP_ASYNC16(dst, src) \
    asm volatile("cp.async.cg.shared.global [%0], [%1], 16;" :: "r"(dst), "l"(src))
#define CP_ASYNC16Z(dst, src, sz) \
    asm volatile("cp.async.cg.shared.global [%0], [%1], 16, %2;" :: "r"(dst), "l"(src), "r"(sz))
#define CP_COMMIT() asm volatile("cp.async.commit_group;" ::: "memory")
#define CP_WAIT(n)  asm volatile("cp.async.wait_group %0;" :: "n"(n) : "memory")

#define LDSM4(r, a) \
    asm volatile("ldmatrix.sync.aligned.m8n8.x4.shared.b16 {%0,%1,%2,%3}, [%4];" \
        : "=r"((r)[0]), "=r"((r)[1]), "=r"((r)[2]), "=r"((r)[3]) : "r"(a))
#define LDSM4T(r, a) \
    asm volatile("ldmatrix.sync.aligned.m8n8.x4.trans.shared.b16 {%0,%1,%2,%3}, [%4];" \
        : "=r"((r)[0]), "=r"((r)[1]), "=r"((r)[2]), "=r"((r)[3]) : "r"(a))

#define MMA16816(d, a, bb0, bb1) \
    asm volatile("mma.sync.aligned.m16n8k16.row.col.f32.bf16.bf16.f32 " \
        "{%0,%1,%2,%3},{%4,%5,%6,%7},{%8,%9},{%0,%1,%2,%3};" \
        : "+f"((d)[0]), "+f"((d)[1]), "+f"((d)[2]), "+f"((d)[3]) \
        : "r"((a)[0]), "r"((a)[1]), "r"((a)[2]), "r"((a)[3]), "r"(bb0), "r"(bb1))

// 32-bf16-wide tile swizzle (64B rows) — fused kernel phase 1
__device__ __forceinline__ uint32_t sw_off(int row, int ch) {
    return (uint32_t)(row * 64 + ((ch ^ ((row >> 1) & 3)) << 4));
}
// 64-bf16-wide tile swizzle (128B rows) — GEMM A stages
__device__ __forceinline__ uint32_t sw128(int row, int ch) {
    return (uint32_t)(row * 128 + ((ch ^ (row & 7)) << 4));
}

// all four weight tensors are 524288 elements each
__global__ void cvt4_k(const float* __restrict__ s0, const float* __restrict__ s1,
                       const float* __restrict__ s2, const float* __restrict__ s3,
                       __nv_bfloat16* __restrict__ d0, __nv_bfloat16* __restrict__ d1,
                       __nv_bfloat16* __restrict__ d2, __nv_bfloat16* __restrict__ d3)
{
    int i = blockIdx.x * 256 + threadIdx.x;
    int seg = i >> 19, off = i & 524287;
    const float* s = (seg == 0) ? s0 : (seg == 1) ? s1 : (seg == 2) ? s2 : s3;
    __nv_bfloat16* d = (seg == 0) ? d0 : (seg == 1) ? d1 : (seg == 2) ? d2 : d3;
    d[off] = __float2bfloat16(s[off]);
}

// ------------------------- merged projection GEMM ----------------------------
// B consumed DIRECTLY from fp32 NCHW x/x_ref (no transpose kernel):
//   stage fp32 [64 k-rows][128 p] via cp.async, convert in-kernel to bf16
//   [64 k-rows][128 p] (256B rows, xor swizzle), consume via ldmatrix.trans
//   (phase-3-proven pattern). A = bf16 weights, K-major, unchanged.
// SMEM: A dbl 2x16KB @0 | B fp32 dbl 2x32KB @32768 | B bf16 single 16KB @98304
__global__ __launch_bounds__(256, 2)
void proj_gemm(const __nv_bfloat16* __restrict__ wth, const __nv_bfloat16* __restrict__ wgp,
               const float* __restrict__ x, const float* __restrict__ xr,
               const float* __restrict__ bth, const float* __restrict__ bg,
               const float* __restrict__ bphi,
               __nv_bfloat16* __restrict__ thb, __nv_bfloat16* __restrict__ gphib)
{
    extern __shared__ char smem[];

    const int t = threadIdx.x, lane = t & 31, wid = t >> 5;
    const int warp_m = wid >> 2, warp_n = wid & 3;
    const int n = blockIdx.z, pbase = blockIdx.x * 128;
    const int by = blockIdx.y;
    const bool th = (by < 4);
    const int obase = (th ? by : by - 4) * 128;
    const __nv_bfloat16* A = th ? wth : wgp;
    const float* Bx = th ? x : xr;
    __nv_bfloat16* out = th ? thb : gphib;
    const int ldo = th ? CINT : 2 * CINT;
    const float* b0 = th ? bth : bg;
    const float* b1 = th ? bth : bphi;
    const int K = CINF, NC = K >> 6;   // 16

    const __nv_bfloat16* Ab = A + (size_t)obase * K;
    const float* Bb = Bx + (size_t)n * CINF * PIX + pbase;
    const uint32_t sbase = smem_u32(smem);

    float acc[4][4][4];
    #pragma unroll
    for (int mi = 0; mi < 4; mi++)
        #pragma unroll
        for (int ni = 0; ni < 4; ni++)
            #pragma unroll
            for (int r = 0; r < 4; r++) acc[mi][ni][r] = 0.f;

    const int rowL = t >> 3, chL = t & 7;     // A loads
    const int browL = t >> 5, bpcL = t & 31;  // B fp32 loads
    auto issue = [&](int c) {
        const int k0 = c << 6;
        const uint32_t stA = sbase + (c & 1) * 16384;
        const uint32_t stB = sbase + 32768 + (c & 1) * 32768;
        #pragma unroll
        for (int i = 0; i < 4; i++) {
            int row = rowL + i * 32;
            CP_ASYNC16(stA + sw128(row, chL), Ab + (size_t)row * K + k0 + chL * 8);
        }
        #pragma unroll
        for (int i = 0; i < 8; i++) {
            int idx = t + i * 256;
            int kr = idx >> 5, pc = idx & 31;
            CP_ASYNC16(stB + kr * 512 + pc * 16,
                       Bb + (size_t)(k0 + kr) * PIX + pc * 4);
        }
        CP_COMMIT();
    };

    issue(0);
    const int rl = lane & 15, cs = lane >> 4;
    const uint32_t stBH = sbase + 98304;

    for (int c = 0; c < NC; c++) {
        CP_WAIT(0);
        __syncthreads();                       // fp32(c)+A(c) ready; prev MMA reads done

        // convert fp32 [64][128p] -> bf16 [64][256B rows, xor swizzle]
        const uint32_t stBF = sbase + 32768 + (c & 1) * 32768;
        #pragma unroll
        for (int i = 0; i < 4; i++) {
            int idx = t + i * 256;
            int kr = idx >> 4, cg = idx & 15;
            float4 a4 = *(float4*)(smem + (stBF - sbase) + kr * 512 + cg * 32);
            float4 b4 = *(float4*)(smem + (stBF - sbase) + kr * 512 + cg * 32 + 16);
            __nv_bfloat162 q0 = __floats2bfloat162_rn(a4.x, a4.y);
            __nv_bfloat162 q1 = __floats2bfloat162_rn(a4.z, a4.w);
            __nv_bfloat162 q2 = __floats2bfloat162_rn(b4.x, b4.y);
            __nv_bfloat162 q3 = __floats2bfloat162_rn(b4.z, b4.w);
            uint4 u;
            u.x = *(uint32_t*)&q0; u.y = *(uint32_t*)&q1;
            u.z = *(uint32_t*)&q2; u.w = *(uint32_t*)&q3;
            *(uint4*)(smem + 98304 + kr * 256 + ((cg ^ (kr & 7)) << 4)) = u;
        }
        if (c + 1 < NC) issue(c + 1);
        __syncthreads();                       // bf16 tile visible

        const uint32_t stA = sbase + (c & 1) * 16384;
        #pragma unroll
        for (int kh = 0; kh < 4; kh++) {
            const int ch = 2 * kh + cs;
            const int r = kh * 16 + rl;
            uint32_t af[4][4], bm[2][4];
            #pragma unroll
            for (int mi = 0; mi < 4; mi++)
                LDSM4(af[mi], stA + sw128(warp_m * 64 + mi * 16 + rl, ch));
            #pragma unroll
            for (int g = 0; g < 2; g++) {
                const int c16 = warp_n * 4 + g * 2 + cs;
                LDSM4T(bm[g], stBH + r * 256 + ((c16 ^ (r & 7)) << 4));
            }
            #pragma unroll
            for (int mi = 0; mi < 4; mi++)
                #pragma unroll
                for (int g = 0; g < 2; g++) {
                    MMA16816(acc[mi][2 * g + 0], af[mi], bm[g][0], bm[g][1]);
                    MMA16816(acc[mi][2 * g + 1], af[mi], bm[g][2], bm[g][3]);
                }
        }
    }

    // epilogue: transpose via SMEM -> coalesced bf16 NHWC rows
    __syncthreads();
    __nv_bfloat16* S = (__nv_bfloat16*)smem;   // [128 p][136 o]
    #pragma unroll
    for (int mi = 0; mi < 4; mi++) {
        #pragma unroll
        for (int h = 0; h < 2; h++) {
            const int ol = warp_m * 64 + mi * 16 + (lane >> 2) + h * 8;
            const int og = obase + ol;
            const float bias = (og < CINT) ? b0[og] : b1[og - CINT];
            #pragma unroll
            for (int ni = 0; ni < 4; ni++) {
                const int pl = warp_n * 32 + ni * 8 + (lane & 3) * 2;
                S[(size_t)pl * 136 + ol]       = __float2bfloat16(acc[mi][ni][2 * h + 0] + bias);
                S[(size_t)(pl + 1) * 136 + ol] = __float2bfloat16(acc[mi][ni][2 * h + 1] + bias);
            }
        }
    }
    __syncthreads();
    #pragma unroll
    for (int s = 0; s < 16; s++) {
        const int pl = s * 8 + wid;
        uint2 v = *(uint2*)&S[(size_t)pl * 136 + lane * 4];
        *(uint2*)(out + ((size_t)n * PIX + pbase + pl) * ldo + obase + lane * 4) = v;
    }
}

// ------------------------- final GEMM (residual, fp32 NCHW) ------------------
// (byte-exact R10 version)
__global__ __launch_bounds__(256, 2)
void final_gemm(const __nv_bfloat16* __restrict__ A, const __nv_bfloat16* __restrict__ B,
                const float* __restrict__ b0, float* __restrict__ out,
                const float* __restrict__ resid)
{
    extern __shared__ char smem[];   // 2 stages x 32KB

    const int t = threadIdx.x, lane = t & 31, wid = t >> 5;
    const int warp_m = wid >> 2, warp_n = wid & 3;
    const int n = blockIdx.z, pbase = blockIdx.x * 128, obase = blockIdx.y * 128;
    const int K = CINT, NC = K >> 6;   // 8

    const __nv_bfloat16* Ab = A + (size_t)obase * K;
    const __nv_bfloat16* Bb = B + ((size_t)n * PIX + pbase) * K;
    const uint32_t sbase = smem_u32(smem);

    float acc[4][4][4];
    #pragma unroll
    for (int mi = 0; mi < 4; mi++)
        #pragma unroll
        for (int ni = 0; ni < 4; ni++)
            #pragma unroll
            for (int r = 0; r < 4; r++) acc[mi][ni][r] = 0.f;

    const int rowL = t >> 3, chL = t & 7;
    auto issue = [&](int c) {
        const int k0 = c << 6;
        const uint32_t st = sbase + (c & 1) * 32768;
        #pragma unroll
        for (int i = 0; i < 4; i++) {
            int row = rowL + i * 32;
            CP_ASYNC16(st + sw128(row, chL), Ab + (size_t)row * K + k0 + chL * 8);
        }
        #pragma unroll
        for (int i = 0; i < 4; i++) {
            int row = rowL + i * 32;
            CP_ASYNC16(st + 16384 + sw128(row, chL), Bb + (size_t)row * K + k0 + chL * 8);
        }
        CP_COMMIT();
    };

    issue(0);
    const int rl = lane & 15, cs = lane >> 4;

    for (int c = 0; c < NC; c++) {
        CP_WAIT(0);
        __syncthreads();
        if (c + 1 < NC) issue(c + 1);

        const uint32_t stA = sbase + (c & 1) * 32768;
        const uint32_t stB = stA + 16384;
        #pragma unroll
        for (int kh = 0; kh < 4; kh++) {
            const int ch = 2 * kh + cs;
            uint32_t af[4][4], bf[2][4];
            #pragma unroll
            for (int mi = 0; mi < 4; mi++)
                LDSM4(af[mi], stA + sw128(warp_m * 64 + mi * 16 + rl, ch));
            #pragma unroll
            for (int g = 0; g < 2; g++)
                LDSM4(bf[g], stB + sw128(warp_n * 32 + g * 16 + rl, ch));
            #pragma unroll
            for (int mi = 0; mi < 4; mi++)
                #pragma unroll
                for (int g = 0; g < 2; g++) {
                    MMA16816(acc[mi][2 * g + 0], af[mi], bf[g][0], bf[g][2]);
                    MMA16816(acc[mi][2 * g + 1], af[mi], bf[g][1], bf[g][3]);
                }
        }
    }

    float* Es = (float*)smem;   // [64 o][132 p]
    #pragma unroll
    for (int og = 0; og < 2; og++) {
        __syncthreads();
        if (warp_m == og) {
            #pragma unroll
            for (int mi = 0; mi < 4; mi++)
                #pragma unroll
                for (int h = 0; h < 2; h++) {
                    const int row = mi * 16 + (lane >> 2) + h * 8;
                    #pragma unroll
                    for (int ni = 0; ni < 4; ni++) {
                        const int col = warp_n * 32 + ni * 8 + (lane & 3) * 2;
                        Es[(size_t)row * 132 + col]     = acc[mi][ni][2 * h + 0];
                        Es[(size_t)row * 132 + col + 1] = acc[mi][ni][2 * h + 1];
                    }
                }
        }
        __syncthreads();
        #pragma unroll
        for (int s = 0; s < 8; s++) {
            const int row = s * 8 + wid;
            const int o = obase + og * 64 + row;
            const size_t addr = ((size_t)n * CINF + o) * PIX + pbase + lane * 4;
            float4 e = *(float4*)&Es[(size_t)row * 132 + lane * 4];
            float4 r = *(const float4*)(resid + addr);
            const float bias = b0[o];
            float4 v;
            v.x = e.x + bias + r.x; v.y = e.y + bias + r.y;
            v.z = e.z + bias + r.z; v.w = e.w + bias + r.w;
            *(float4*)(out + addr) = v;
        }
    }
}

// ------------------------- fused corr + softmax + assemble -------------------
// (byte-exact R10 85us version)
__global__ __launch_bounds__(256, 2)
void fused_attn_k(const __nv_bfloat16* __restrict__ theta,
                  const __nv_bfloat16* __restrict__ gphi,
                  __nv_bfloat16* __restrict__ y)
{
    extern __shared__ char smem[];
    char*  Xr   = smem + 33792;
    float* Cs   = (float*)Xr;                       // [64][266] fp32
    float* invs = (float*)(smem + 33792 + 68096);   // [64]

    const int t = threadIdx.x, lane = t & 31, wid = t >> 5;
    const int warp_m = wid >> 2, warp_n = wid & 3;  // 2 x 4
    const int rl = lane & 15, cs = lane >> 4;
    const int n = blockIdx.z, h0 = blockIdx.y * 8, w0 = blockIdx.x * 8;

    const uint32_t sbX  = smem_u32(Xr);
    const uint32_t sbPW = smem_u32(smem);

    float acc[2][8][4];
    #pragma unroll
    for (int a = 0; a < 2; a++)
        #pragma unroll
        for (int b = 0; b < 8; b++)
            #pragma unroll
            for (int c = 0; c < 4; c++) acc[a][b][c] = 0.f;

    // ---------------- phase 1: corr GEMM ----------------
    const int rowA = t >> 2, chA = t & 3;
    const __nv_bfloat16* thsrc =
        theta + ((size_t)n * PIX + (h0 + (rowA >> 3)) * WDIM + (w0 + (rowA & 7))) * CINT + chA * 8;

    const __nv_bfloat16* phsrc[4];
    uint32_t phok[4]; int phrow[4], phch[4];
    #pragma unroll
    for (int i = 0; i < 4; i++) {
        int idx = t + i * 256;
        int row = idx >> 2, ch = idx & 3;
        int hy = h0 + (row >> 4) - DD, hx = w0 + (row & 15) - DD;
        bool ok = (hy >= 0 && hy < HDIM && hx >= 0 && hx < WDIM);
        phrow[i] = row; phch[i] = ch; phok[i] = ok ? 16u : 0u;
        phsrc[i] = gphi + (ok ? (((size_t)n * PIX + hy * WDIM + hx) * 1024 + 512 + ch * 8) : 0);
    }

    auto issue1 = [&](int c) {
        const int c0 = c << 5;
        const uint32_t st = sbX + (c % 3) * 20480;
        CP_ASYNC16(st + sw_off(rowA, chA), thsrc + c0);
        #pragma unroll
        for (int i = 0; i < 4; i++)
            CP_ASYNC16Z(st + 4096 + sw_off(phrow[i], phch[i]),
                        phsrc[i] + (phok[i] ? c0 : 0), phok[i]);
        CP_COMMIT();
    };

    issue1(0); issue1(1);
    for (int c = 0; c < 16; c++) {
        if (c < 15) CP_WAIT(1); else CP_WAIT(0);
        __syncthreads();
        if (c + 2 < 16) issue1(c + 2);
        const uint32_t stA = sbX + (c % 3) * 20480;
        const uint32_t stB = stA + 4096;
        #pragma unroll
        for (int kh = 0; kh < 2; kh++) {
            const int ch = 2 * kh + cs;
            uint32_t af[2][4], bm[4][4];
            #pragma unroll
            for (int mi = 0; mi < 2; mi++)
                LDSM4(af[mi], stA + sw_off(warp_m * 32 + mi * 16 + rl, ch));
            #pragma unroll
            for (int nf = 0; nf < 4; nf++)
                LDSM4(bm[nf], stB + sw_off(warp_n * 64 + nf * 16 + rl, ch));
            #pragma unroll
            for (int mi = 0; mi < 2; mi++)
                #pragma unroll
                for (int nf = 0; nf < 4; nf++) {
                    MMA16816(acc[mi][2 * nf + 0], af[mi], bm[nf][0], bm[nf][2]);
                    MMA16816(acc[mi][2 * nf + 1], af[mi], bm[nf][1], bm[nf][3]);
                }
        }
    }
    __syncthreads();   // stages dead; write C to smem (overlays stage region)

    #pragma unroll
    for (int mi = 0; mi < 2; mi++)
        #pragma unroll
        for (int ni = 0; ni < 8; ni++) {
            const int r0  = warp_m * 32 + mi * 16 + (lane >> 2);
            const int col = warp_n * 64 + ni * 8 + 2 * (lane & 3);
            *(float2*)&Cs[(size_t)r0 * 266 + col]       = make_float2(acc[mi][ni][0], acc[mi][ni][1]);
            *(float2*)&Cs[(size_t)(r0 + 8) * 266 + col] = make_float2(acc[mi][ni][2], acc[mi][ni][3]);
        }
    __syncthreads();

    // ---------------- phase 2: softmax -> PW bf16 ----------------
    if (t < 64) {
        const int py = t >> 3, pxx = t & 7;
        uint32_t* pwz = (uint32_t*)(smem + t * 528);
        #pragma unroll 4
        for (int i = 0; i < 132; i++) pwz[i] = 0;
        const float SC = 0.051031036307982884f;   // 256/(512*sqrt(96))
        float m = -1e30f;
        #pragma unroll
        for (int dy = 0; dy < QD; dy++)
            #pragma unroll
            for (int dx = 0; dx < QD; dx++)
                m = fmaxf(m, Cs[(size_t)t * 266 + (py + dy) * 16 + pxx + dx] * SC);
        float s = 0.f;
        __nv_bfloat16* pwrow = (__nv_bfloat16*)(smem + t * 528);
        #pragma unroll
        for (int dy = 0; dy < QD; dy++)
            #pragma unroll
            for (int dx = 0; dx < QD; dx++) {
                const int col = (py + dy) * 16 + pxx + dx;
                float e = __expf(Cs[(size_t)t * 266 + col] * SC - m);
                s += e;
                pwrow[col] = __float2bfloat16(e);
            }
        invs[t] = 1.f / s;
    }
    __syncthreads();

    // ---------------- phase 3: assemble GEMM ----------------
    for (int half = 0; half < 2; half++) {
        const int cbase = half * 256;
        #pragma unroll
        for (int a = 0; a < 2; a++)
            #pragma unroll
            for (int b = 0; b < 8; b++)
                #pragma unroll
                for (int c = 0; c < 4; c++) acc[a][b][c] = 0.f;

        auto issue3 = [&](int kk) {
            const uint32_t st = sbX + (kk % 3) * 16384;
            #pragma unroll
            for (int i = 0; i < 4; i++) {
                int idx = t + i * 256;
                int row = idx >> 5, ch = idx & 31;
                int hp = kk * 32 + row;
                int hy = h0 + (hp >> 4) - DD, hx = w0 + (hp & 15) - DD;
                bool ok = (hy >= 0 && hy < HDIM && hx >= 0 && hx < WDIM);
                const __nv_bfloat16* src = gphi +
                    (ok ? (((size_t)n * PIX + hy * WDIM + hx) * 1024 + cbase + ch * 8) : 0);
                CP_ASYNC16Z(st + row * 512 + ((ch ^ (row & 7)) << 4), src, ok ? 16u : 0u);
            }
            CP_COMMIT();
        };

        issue3(0); issue3(1);
        for (int kk = 0; kk < 8; kk++) {
            if (kk < 7) CP_WAIT(1); else CP_WAIT(0);
            __syncthreads();
            if (kk + 2 < 8) issue3(kk + 2);
            const uint32_t st = sbX + (kk % 3) * 16384;
            #pragma unroll
            for (int kh = 0; kh < 2; kh++) {
                uint32_t af[2][4], bm[4][4];
                const int chunk = kk * 4 + kh * 2 + cs;
                #pragma unroll
                for (int mi = 0; mi < 2; mi++)
                    LDSM4(af[mi], sbPW + (warp_m * 32 + mi * 16 + rl) * 528 + chunk * 16);
                const int r = kh * 16 + rl;
                #pragma unroll
                for (int nf = 0; nf < 4; nf++) {
                    const int c16 = warp_n * 8 + nf * 2 + cs;
                    LDSM4T(bm[nf], st + r * 512 + ((c16 ^ (r & 7)) << 4));
                }
                #pragma unroll
                for (int mi = 0; mi < 2; mi++)
                    #pragma unroll
                    for (int nf = 0; nf < 4; nf++) {
                        MMA16816(acc[mi][2 * nf + 0], af[mi], bm[nf][0], bm[nf][1]);
                        MMA16816(acc[mi][2 * nf + 1], af[mi], bm[nf][2], bm[nf][3]);
                    }
            }
        }

        #pragma unroll
        for (int mi = 0; mi < 2; mi++)
            #pragma unroll
            for (int ni = 0; ni < 8; ni++) {
                const int r0 = warp_m * 32 + mi * 16 + (lane >> 2);
                const int cc = cbase + warp_n * 64 + ni * 8 + 2 * (lane & 3);
                #pragma unroll
                for (int hh = 0; hh < 2; hh++) {
                    const int px = r0 + hh * 8;
                    const float is = invs[px];
                    const size_t addr =
                        ((size_t)n * PIX + (h0 + (px >> 3)) * WDIM + (w0 + (px & 7))) * CINT + cc;
                    __nv_bfloat162 pk = __floats2bfloat162_rn(acc[mi][ni][2 * hh + 0] * is,
                                                              acc[mi][ni][2 * hh + 1] * is);
                    *(__nv_bfloat162*)(y + addr) = pk;
                }
            }
        __syncthreads();
    }
}

// ---------------------------------------------------------------------------
extern "C" void kernel_launch(void* const* d_in, const int* in_sizes, int n_in,
                              void* d_out, int out_size)
{
    (void)in_sizes; (void)n_in; (void)out_size;
    const float* x       = (const float*)d_in[0];
    const float* x_ref   = (const float*)d_in[1];
    const float* w_g     = (const float*)d_in[2];
    const float* b_g     = (const float*)d_in[3];
    const float* w_theta = (const float*)d_in[4];
    const float* b_theta = (const float*)d_in[5];
    const float* w_phi   = (const float*)d_in[6];
    const float* b_phi   = (const float*)d_in[7];
    const float* w_out   = (const float*)d_in[8];
    const float* b_out   = (const float*)d_in[9];
    float* out = (float*)d_out;

    __nv_bfloat16 *thb_d, *gphib_d, *ybf_d, *wth_d, *wgp_d, *wo_d;
    cudaGetSymbolAddress((void**)&thb_d,   g_thb);
    cudaGetSymbolAddress((void**)&gphib_d, g_gphib);
    cudaGetSymbolAddress((void**)&ybf_d,   g_ybf);
    cudaGetSymbolAddress((void**)&wth_d,   g_wth);
    cudaGetSymbolAddress((void**)&wgp_d,   g_wgp);
    cudaGetSymbolAddress((void**)&wo_d,    g_wo);

    const int FUSED_SMEM = 33792 + 68096 + 256;   // 102144 (2 CTAs/SM)
    const int PROJ_SMEM  = 98304 + 16384;         // 114688 (2 CTAs/SM: 224KB)
    const int FIN_SMEM   = 2 * 32768;             // 65536
    cudaFuncSetAttribute(fused_attn_k, cudaFuncAttributeMaxDynamicSharedMemorySize, FUSED_SMEM);
    cudaFuncSetAttribute(proj_gemm,   cudaFuncAttributeMaxDynamicSharedMemorySize, PROJ_SMEM);
    cudaFuncSetAttribute(final_gemm,  cudaFuncAttributeMaxDynamicSharedMemorySize, FIN_SMEM);

    // 1: weight conversions
    cvt4_k<<<8192, 256>>>(w_theta, w_g, w_phi, w_out,
                          wth_d, wgp_d, wgp_d + (size_t)CINT * CINF, wo_d);

    // 2: merged theta + (g;phi) projections, B direct from fp32 NCHW
    proj_gemm<<<dim3(72, 12, NB), 256, PROJ_SMEM>>>(
        wth_d, wgp_d, x, x_ref, b_theta, b_g, b_phi, thb_d, gphib_d);

    // 3: fused corr + softmax + assemble -> y bf16 [p][512]
    fused_attn_k<<<dim3(12, 12, NB), 256, FUSED_SMEM>>>(thb_d, gphib_d, ybf_d);

    // 4: out = x + w_out @ y + b_out (fp32 NCHW)
    final_gemm<<<dim3(72, 8, NB), 256, FIN_SMEM>>>(wo_d, ybf_d, b_out, out, x);
}